// round 10
// baseline (speedup 1.0000x reference)
#include <cuda_runtime.h>
#include <cuda_bf16.h>
#include <cstdint>

#define BB 64
#define TT 256
#define CC 384
#define HH 6
#define DD 64
#define BT (BB*TT)         // 16384
#define NQKV (3*HH*DD)     // 1152
#define PITCH 40           // bf16 elems per smem/gmem tile row
#define TILE_E 5120        // elems per 128x32 tile (with pitch 40)
#define TILE_B 10240       // bytes per tile
#define NCH 12             // K chunks (384/32)

// prep work partition (8 elems per thread)
#define XW (BT*CC/8)       // 786432
#define WTW (NQKV*CC/8)    // 55296
#define WPW (CC*CC/8)      // 18432

// attention smem layout (bytes). Q/K pitch 72 bf16 (144B), Vt pitch 264 bf16 (528B)
#define AQH 0
#define AQL 36864
#define AKH 73728
#define AKL 110592
#define AVH 147456
#define AVL 181248
#define ASZ 215040

// ---------------- static scratch (tiled/pitched layouts) ----------------
__device__ __align__(128) __nv_bfloat16 g_Xhi[(size_t)128*NCH*TILE_E], g_Xlo[(size_t)128*NCH*TILE_E];
__device__ __align__(128) __nv_bfloat16 g_Wthi[(size_t)9*NCH*TILE_E],  g_Wtlo[(size_t)9*NCH*TILE_E];
__device__ __align__(128) __nv_bfloat16 g_Athi[(size_t)128*NCH*TILE_E],g_Atlo[(size_t)128*NCH*TILE_E];
__device__ __align__(128) __nv_bfloat16 g_Wphi[(size_t)3*NCH*TILE_E],  g_Wplo[(size_t)3*NCH*TILE_E];
__device__ __align__(128) __nv_bfloat16 g_Qh[(size_t)BB*HH*TT*72], g_Ql[(size_t)BB*HH*TT*72];
__device__ __align__(128) __nv_bfloat16 g_Kh[(size_t)BB*HH*TT*72], g_Kl[(size_t)BB*HH*TT*72];
__device__ __align__(128) __nv_bfloat16 g_Vth[(size_t)BB*HH*DD*264], g_Vtl[(size_t)BB*HH*DD*264];

// ---------------- helpers ----------------
__device__ __forceinline__ void bulk_g2s(uint32_t dst, const void* src, uint32_t bytes,
                                         uint32_t mbar) {
    asm volatile("cp.async.bulk.shared::cluster.global.mbarrier::complete_tx::bytes "
                 "[%0], [%1], %2, [%3];"
                 :: "r"(dst), "l"(src), "r"(bytes), "r"(mbar) : "memory");
}
__device__ __forceinline__ void mbar_init(uint32_t mbar, uint32_t cnt) {
    asm volatile("mbarrier.init.shared.b64 [%0], %1;" :: "r"(mbar), "r"(cnt) : "memory");
}
__device__ __forceinline__ void mbar_expect(uint32_t mbar, uint32_t bytes) {
    asm volatile("mbarrier.arrive.expect_tx.shared.b64 _, [%0], %1;"
                 :: "r"(mbar), "r"(bytes) : "memory");
}
__device__ __forceinline__ void mbar_arrive(uint32_t mbar) {
    asm volatile("mbarrier.arrive.shared.b64 _, [%0];" :: "r"(mbar) : "memory");
}
__device__ __forceinline__ void mbar_wait(uint32_t mbar, uint32_t parity) {
    asm volatile("{\n\t.reg .pred P;\n\t"
                 "WL_%=:\n\t"
                 "mbarrier.try_wait.parity.acquire.cta.shared::cta.b64 P, [%0], %1, 0x989680;\n\t"
                 "@P bra WD_%=;\n\t"
                 "bra WL_%=;\n\t"
                 "WD_%=:\n\t}"
                 :: "r"(mbar), "r"(parity) : "memory");
}
__device__ __forceinline__ void fence_async() {
    asm volatile("fence.proxy.async.shared::cta;" ::: "memory");
}
__device__ __forceinline__ void mma_bf16(float* c, const uint32_t* a, const uint32_t* b) {
    asm volatile("mma.sync.aligned.m16n8k16.row.col.f32.bf16.bf16.f32 "
                 "{%0,%1,%2,%3}, {%4,%5,%6,%7}, {%8,%9}, {%0,%1,%2,%3};"
                 : "+f"(c[0]), "+f"(c[1]), "+f"(c[2]), "+f"(c[3])
                 : "r"(a[0]), "r"(a[1]), "r"(a[2]), "r"(a[3]),
                   "r"(b[0]), "r"(b[1]));
}
__device__ __forceinline__ void ldm_x4(uint32_t* r, uint32_t addr) {
    asm volatile("ldmatrix.sync.aligned.m8n8.x4.shared.b16 {%0,%1,%2,%3}, [%4];"
                 : "=r"(r[0]), "=r"(r[1]), "=r"(r[2]), "=r"(r[3]) : "r"(addr));
}
__device__ __forceinline__ void split2(float x, float y, uint32_t& hi, uint32_t& lo) {
    __nv_bfloat16 hx = __float2bfloat16(x), hy = __float2bfloat16(y);
    __nv_bfloat16 lx = __float2bfloat16(x - __bfloat162float(hx));
    __nv_bfloat16 ly = __float2bfloat16(y - __bfloat162float(hy));
    uint16_t uhx = *(uint16_t*)&hx, uhy = *(uint16_t*)&hy;
    uint16_t ulx = *(uint16_t*)&lx, uly = *(uint16_t*)&ly;
    hi = (uint32_t)uhx | ((uint32_t)uhy << 16);
    lo = (uint32_t)ulx | ((uint32_t)uly << 16);
}
__device__ __forceinline__ size_t tiled_idx(int m, int k) {   // 128-row blocks, 32-col chunks
    return ((size_t)(m >> 7) * NCH + (k >> 5)) * TILE_E + (m & 127) * PITCH + (k & 31);
}

// ---------------- fused prep: split X, pack+split Wt, split Wp ----------------
__global__ void prep(const float* __restrict__ x,
                     const float* __restrict__ Wq, const float* __restrict__ Wk,
                     const float* __restrict__ Wv, const float* __restrict__ Wp) {
    int g = blockIdx.x * blockDim.x + threadIdx.x;
    if (g < XW) {
        int i = g * 8;
        int m = i / CC, k = i % CC;
        float4 v0 = *(const float4*)(x + i);
        float4 v1 = *(const float4*)(x + i + 4);
        __nv_bfloat16 h[8], l[8];
        float vv[8] = {v0.x,v0.y,v0.z,v0.w,v1.x,v1.y,v1.z,v1.w};
        #pragma unroll
        for (int j = 0; j < 8; j++) {
            h[j] = __float2bfloat16(vv[j]);
            l[j] = __float2bfloat16(vv[j] - __bfloat162float(h[j]));
        }
        size_t d = tiled_idx(m, k);
        *(uint4*)(g_Xhi + d) = *(uint4*)h;
        *(uint4*)(g_Xlo + d) = *(uint4*)l;
    } else if (g < XW + WTW) {
        int idx8 = g - XW;
        int n = idx8 / (CC/8), c0 = (idx8 % (CC/8)) * 8;
        int proj = n / (HH * DD), r = n % (HH * DD);
        int h = r / DD, d = r % DD;
        const float* W = (proj == 0) ? Wq : (proj == 1) ? Wk : Wv;
        size_t o = tiled_idx(n, c0);
        #pragma unroll
        for (int cc = 0; cc < 8; cc++) {
            float v = W[((size_t)h * CC + c0 + cc) * DD + d];
            __nv_bfloat16 hi = __float2bfloat16(v);
            g_Wthi[o + cc] = hi;
            g_Wtlo[o + cc] = __float2bfloat16(v - __bfloat162float(hi));
        }
    } else if (g < XW + WTW + WPW) {
        int i = (g - XW - WTW) * 8;
        int n = i / CC, k = i % CC;
        float4 v0 = *(const float4*)(Wp + i);
        float4 v1 = *(const float4*)(Wp + i + 4);
        __nv_bfloat16 h[8], l[8];
        float vv[8] = {v0.x,v0.y,v0.z,v0.w,v1.x,v1.y,v1.z,v1.w};
        #pragma unroll
        for (int j = 0; j < 8; j++) {
            h[j] = __float2bfloat16(vv[j]);
            l[j] = __float2bfloat16(vv[j] - __bfloat162float(h[j]));
        }
        size_t d = tiled_idx(n, k);
        *(uint4*)(g_Wphi + d) = *(uint4*)h;
        *(uint4*)(g_Wplo + d) = *(uint4*)l;
    }
}

// ---------------------------------------------------------------------------
// HMMA GEMM: bulk staging, ldmatrix frags, async buffer recycle (no syncthreads
// in main loop): full mbarriers (tx) + empty mbarriers (8 warp arrivals).
// ---------------------------------------------------------------------------
template<int MODE>
__global__ __launch_bounds__(256, 2) void gemm_tc(const float* __restrict__ bp,
                                                  float* __restrict__ outp) {
    extern __shared__ __align__(128) char sm[];
    const __nv_bfloat16* Ahi = (MODE == 0) ? g_Xhi  : g_Athi;
    const __nv_bfloat16* Alo = (MODE == 0) ? g_Xlo  : g_Atlo;
    const __nv_bfloat16* Bhi = (MODE == 0) ? g_Wthi : g_Wphi;
    const __nv_bfloat16* Blo = (MODE == 0) ? g_Wtlo : g_Wplo;

    const int tid = threadIdx.x, lane = tid & 31, wid = tid >> 5;
    const int wm = wid & 3, wn = wid >> 2;
    const int lr = lane >> 2, lc = lane & 3;
    const int rb = blockIdx.y, cb = blockIdx.x;
    const int row0 = rb * 128, col0 = cb * 128;
    const uint32_t sbase = (uint32_t)__cvta_generic_to_shared(sm);
    const uint32_t fullb0  = sbase + 8*TILE_B,      fullb1  = fullb0 + 8;
    const uint32_t emptyb0 = fullb0 + 16,           emptyb1 = fullb0 + 24;

    uint32_t aoff[2];
    #pragma unroll
    for (int mt = 0; mt < 2; mt++)
        aoff[mt] = (uint32_t)(wm*32 + mt*16 + (lane & 15)) * PITCH + ((lane >> 4) & 1) * 8;
    uint32_t boff[4];
    #pragma unroll
    for (int jj = 0; jj < 4; jj++)
        boff[jj] = (uint32_t)(wn*64 + jj*16 + ((lane >> 4) & 1)*8 + (lane & 7)) * PITCH
                   + ((lane >> 3) & 1) * 8;

    if (tid == 0) {
        mbar_init(fullb0, 1);  mbar_init(fullb1, 1);
        mbar_init(emptyb0, 8); mbar_init(emptyb1, 8);
    }
    __syncthreads();

    auto issue = [&](int buf, int c) {
        uint32_t st = sbase + buf * 4 * TILE_B;
        uint32_t mb = buf ? fullb1 : fullb0;
        fence_async();
        mbar_expect(mb, 4 * TILE_B);
        bulk_g2s(st + 0*TILE_B, Ahi + ((size_t)rb*NCH + c)*TILE_E, TILE_B, mb);
        bulk_g2s(st + 1*TILE_B, Alo + ((size_t)rb*NCH + c)*TILE_E, TILE_B, mb);
        bulk_g2s(st + 2*TILE_B, Bhi + ((size_t)cb*NCH + c)*TILE_E, TILE_B, mb);
        bulk_g2s(st + 3*TILE_B, Blo + ((size_t)cb*NCH + c)*TILE_E, TILE_B, mb);
    };

    float acc[2][8][4];
    #pragma unroll
    for (int i = 0; i < 2; i++)
        #pragma unroll
        for (int j = 0; j < 8; j++)
            #pragma unroll
            for (int r = 0; r < 4; r++) acc[i][j][r] = 0.f;

    if (tid == 0) { issue(0, 0); issue(1, 1); }

    for (int kc = 0; kc < NCH; kc++) {
        int buf = kc & 1;
        mbar_wait(buf ? fullb1 : fullb0, (kc >> 1) & 1);

        const uint32_t sbuf = sbase + buf * 4 * TILE_B;
        #pragma unroll
        for (int ks = 0; ks < 2; ks++) {
            const uint32_t kb = ks * 16;
            uint32_t ah[2][4], al[2][4];
            #pragma unroll
            for (int mt = 0; mt < 2; mt++) {
                uint32_t ad = sbuf + (aoff[mt] + kb) * 2;
                ldm_x4(ah[mt], ad);
                ldm_x4(al[mt], ad + TILE_B);
            }
            #pragma unroll
            for (int jj = 0; jj < 4; jj++) {
                uint32_t bd = sbuf + 2*TILE_B + (boff[jj] + kb) * 2;
                uint32_t bh4[4], bl4[4];
                ldm_x4(bh4, bd);
                ldm_x4(bl4, bd + TILE_B);
                #pragma unroll
                for (int mt = 0; mt < 2; mt++) {
                    mma_bf16(acc[mt][2*jj],   ah[mt], bh4);
                    mma_bf16(acc[mt][2*jj],   ah[mt], bl4);
                    mma_bf16(acc[mt][2*jj],   al[mt], bh4);
                    mma_bf16(acc[mt][2*jj+1], ah[mt], bh4 + 2);
                    mma_bf16(acc[mt][2*jj+1], ah[mt], bl4 + 2);
                    mma_bf16(acc[mt][2*jj+1], al[mt], bh4 + 2);
                }
            }
        }
        // all smem reads for this buffer done (regs only below) -> release buffer
        if (lane == 0) mbar_arrive(buf ? emptyb1 : emptyb0);
        if (tid == 0 && kc + 2 < NCH) {
            mbar_wait(buf ? emptyb1 : emptyb0, (kc >> 1) & 1);
            issue(buf, kc + 2);
        }
    }

    // epilogue
    #pragma unroll
    for (int i = 0; i < 2; i++) {
        int m0 = row0 + wm*32 + i*16 + lr;
        #pragma unroll
        for (int j = 0; j < 8; j++) {
            int nn = col0 + wn*64 + j*8 + lc*2;
            if (MODE == 0) {
                int proj = nn / (HH*DD);
                int rem  = nn % (HH*DD);
                int h = rem / DD, d = rem % DD;
                int b = m0 / TT, t = m0 % TT;
                int bh = b*HH + h;
                if (proj < 2) {
                    __nv_bfloat16* dh = (proj == 0) ? g_Qh : g_Kh;
                    __nv_bfloat16* dl = (proj == 0) ? g_Ql : g_Kl;
                    uint32_t h01, l01, h23, l23;
                    split2(acc[i][j][0], acc[i][j][1], h01, l01);
                    split2(acc[i][j][2], acc[i][j][3], h23, l23);
                    size_t o = ((size_t)bh*TT + t)*72 + d;
                    *(uint32_t*)(dh + o) = h01;          *(uint32_t*)(dl + o) = l01;
                    *(uint32_t*)(dh + o + 8*72) = h23;   *(uint32_t*)(dl + o + 8*72) = l23;
                } else {
                    size_t o = ((size_t)bh*DD + d)*264 + t;
                    float v00 = acc[i][j][0], v01 = acc[i][j][1];
                    float v10 = acc[i][j][2], v11 = acc[i][j][3];
                    __nv_bfloat16 hv, lv;
                    hv = __float2bfloat16(v00); lv = __float2bfloat16(v00 - __bfloat162float(hv));
                    g_Vth[o] = hv;               g_Vtl[o] = lv;
                    hv = __float2bfloat16(v01); lv = __float2bfloat16(v01 - __bfloat162float(hv));
                    g_Vth[o + 264] = hv;         g_Vtl[o + 264] = lv;
                    hv = __float2bfloat16(v10); lv = __float2bfloat16(v10 - __bfloat162float(hv));
                    g_Vth[o + 8] = hv;           g_Vtl[o + 8] = lv;
                    hv = __float2bfloat16(v11); lv = __float2bfloat16(v11 - __bfloat162float(hv));
                    g_Vth[o + 264 + 8] = hv;     g_Vtl[o + 264 + 8] = lv;
                }
            } else {
                float2 bb = *(const float2*)(bp + nn);
                *(float2*)(outp + (size_t)m0 * CC + nn) =
                    make_float2(acc[i][j][0] + bb.x, acc[i][j][1] + bb.y);
                *(float2*)(outp + (size_t)(m0 + 8) * CC + nn) =
                    make_float2(acc[i][j][2] + bb.x, acc[i][j][3] + bb.y);
            }
        }
    }
}

// ---------------------------------------------------------------------------
// HMMA flash attention, LOAD-BALANCED: warp w owns 16-row tiles j=w and j=15-w.
// chunks(j) = j/4+1; every warp does exactly 5 tile-chunks. Q frags hoisted.
// ---------------------------------------------------------------------------
__global__ __launch_bounds__(256, 1) void attn_flash() {
    extern __shared__ __align__(128) char sma[];
    const int bh = blockIdx.x;
    const int tid = threadIdx.x, lane = tid & 31, w = tid >> 5;
    const int lr = lane >> 2, lc = lane & 3;
    const uint32_t sb = (uint32_t)__cvta_generic_to_shared(sma);
    const uint32_t mb = sb + ASZ;

    if (tid == 0) {
        mbar_init(mb, 1);
        fence_async();
        mbar_expect(mb, ASZ);
        bulk_g2s(sb + AQH, g_Qh  + (size_t)bh*TT*72,  36864, mb);
        bulk_g2s(sb + AQL, g_Ql  + (size_t)bh*TT*72,  36864, mb);
        bulk_g2s(sb + AKH, g_Kh  + (size_t)bh*TT*72,  36864, mb);
        bulk_g2s(sb + AKL, g_Kl  + (size_t)bh*TT*72,  36864, mb);
        bulk_g2s(sb + AVH, g_Vth + (size_t)bh*DD*264, 33792, mb);
        bulk_g2s(sb + AVL, g_Vtl + (size_t)bh*DD*264, 33792, mb);
    }
    __syncthreads();
    mbar_wait(mb, 0);

    const int b = bh / HH, h = bh % HH;

    #pragma unroll
    for (int half = 0; half < 2; half++) {
        const int jt = half ? (15 - w) : w;
        const int rowbase = jt * 16;
        const int cnt = (jt >> 2) + 1;
        const int diagc = jt >> 2;

        // hoisted Q fragments (all 4 k-steps)
        uint32_t qh[4][4], ql[4][4];
        #pragma unroll
        for (int ks = 0; ks < 4; ks++) {
            uint32_t off = (uint32_t)(rowbase + lr)*144 + (ks*16 + lc*2)*2;
            qh[ks][0] = *(const uint32_t*)(sma + AQH + off);
            qh[ks][1] = *(const uint32_t*)(sma + AQH + off + 8*144);
            qh[ks][2] = *(const uint32_t*)(sma + AQH + off + 16);
            qh[ks][3] = *(const uint32_t*)(sma + AQH + off + 8*144 + 16);
            ql[ks][0] = *(const uint32_t*)(sma + AQL + off);
            ql[ks][1] = *(const uint32_t*)(sma + AQL + off + 8*144);
            ql[ks][2] = *(const uint32_t*)(sma + AQL + off + 16);
            ql[ks][3] = *(const uint32_t*)(sma + AQL + off + 8*144 + 16);
        }

        float O[8][4];
        #pragma unroll
        for (int j = 0; j < 8; j++)
            #pragma unroll
            for (int r = 0; r < 4; r++) O[j][r] = 0.f;
        float rowm[2] = {-1e30f, -1e30f};
        float rowl[2] = {0.f, 0.f};

        for (int c = 0; c < cnt; c++) {
            const int s0 = c * 64;
            float S[8][4];
            #pragma unroll
            for (int n = 0; n < 8; n++)
                #pragma unroll
                for (int r = 0; r < 4; r++) S[n][r] = 0.f;

            #pragma unroll
            for (int ks = 0; ks < 4; ks++) {
                #pragma unroll
                for (int n = 0; n < 8; n++) {
                    uint32_t off = (uint32_t)(s0 + n*8 + lr)*144 + (ks*16 + lc*2)*2;
                    uint32_t kbh[2], kbl[2];
                    kbh[0] = *(const uint32_t*)(sma + AKH + off);
                    kbh[1] = *(const uint32_t*)(sma + AKH + off + 16);
                    kbl[0] = *(const uint32_t*)(sma + AKL + off);
                    kbl[1] = *(const uint32_t*)(sma + AKL + off + 16);
                    mma_bf16(S[n], qh[ks], kbh);
                    mma_bf16(S[n], qh[ks], kbl);
                    mma_bf16(S[n], ql[ks], kbh);
                }
            }

            const bool diag = (c == diagc);
            const int trow = rowbase + lr;
            #pragma unroll
            for (int n = 0; n < 8; n++) {
                int scol = s0 + n*8 + lc*2;
                S[n][0] *= 0.125f; S[n][1] *= 0.125f;
                S[n][2] *= 0.125f; S[n][3] *= 0.125f;
                if (diag) {
                    if (scol     > trow)     S[n][0] = -1e30f;
                    if (scol + 1 > trow)     S[n][1] = -1e30f;
                    if (scol     > trow + 8) S[n][2] = -1e30f;
                    if (scol + 1 > trow + 8) S[n][3] = -1e30f;
                }
            }

            #pragma unroll
            for (int rg = 0; rg < 2; rg++) {
                float cm = -1e30f;
                #pragma unroll
                for (int n = 0; n < 8; n++) {
                    cm = fmaxf(cm, S[n][rg*2]);
                    cm = fmaxf(cm, S[n][rg*2+1]);
                }
                cm = fmaxf(cm, __shfl_xor_sync(0xffffffffu, cm, 1));
                cm = fmaxf(cm, __shfl_xor_sync(0xffffffffu, cm, 2));
                float mold = rowm[rg];
                float mn = fmaxf(mold, cm);
                float alpha = __expf(mold - mn);
                rowm[rg] = mn;
                float ls = 0.f;
                #pragma unroll
                for (int n = 0; n < 8; n++) {
                    float p0 = __expf(S[n][rg*2]   - mn);
                    float p1 = __expf(S[n][rg*2+1] - mn);
                    S[n][rg*2] = p0; S[n][rg*2+1] = p1;
                    ls += p0 + p1;
                }
                rowl[rg] = rowl[rg]*alpha + ls;
                #pragma unroll
                for (int j = 0; j < 8; j++) {
                    O[j][rg*2]   *= alpha;
                    O[j][rg*2+1] *= alpha;
                }
            }

            #pragma unroll
            for (int ks2 = 0; ks2 < 4; ks2++) {
                uint32_t ph[4], pl[4];
                split2(S[2*ks2][0],   S[2*ks2][1],   ph[0], pl[0]);
                split2(S[2*ks2][2],   S[2*ks2][3],   ph[1], pl[1]);
                split2(S[2*ks2+1][0], S[2*ks2+1][1], ph[2], pl[2]);
                split2(S[2*ks2+1][2], S[2*ks2+1][3], ph[3], pl[3]);
                #pragma unroll
                for (int j = 0; j < 8; j++) {
                    uint32_t off = (uint32_t)(j*8 + lr)*528 + (s0 + ks2*16 + lc*2)*2;
                    uint32_t vbh[2], vbl[2];
                    vbh[0] = *(const uint32_t*)(sma + AVH + off);
                    vbh[1] = *(const uint32_t*)(sma + AVH + off + 16);
                    vbl[0] = *(const uint32_t*)(sma + AVL + off);
                    vbl[1] = *(const uint32_t*)(sma + AVL + off + 16);
                    mma_bf16(O[j], ph, vbh);
                    mma_bf16(O[j], ph, vbl);
                    mma_bf16(O[j], pl, vbh);
                }
            }
        }

        float linv0 , linv1;
        {
            float lf = rowl[0];
            lf += __shfl_xor_sync(0xffffffffu, lf, 1);
            lf += __shfl_xor_sync(0xffffffffu, lf, 2);
            linv0 = 1.f / lf;
            lf = rowl[1];
            lf += __shfl_xor_sync(0xffffffffu, lf, 1);
            lf += __shfl_xor_sync(0xffffffffu, lf, 2);
            linv1 = 1.f / lf;
        }
        const int gm0 = b*TT + rowbase + lr;
        #pragma unroll
        for (int j = 0; j < 8; j++) {
            int n = h*DD + j*8 + lc*2;
            uint32_t hi, lo;
            size_t o0 = tiled_idx(gm0, n);
            split2(O[j][0]*linv0, O[j][1]*linv0, hi, lo);
            *(uint32_t*)(g_Athi + o0) = hi;  *(uint32_t*)(g_Atlo + o0) = lo;
            size_t o1 = tiled_idx(gm0 + 8, n);
            split2(O[j][2]*linv1, O[j][3]*linv1, hi, lo);
            *(uint32_t*)(g_Athi + o1) = hi;  *(uint32_t*)(g_Atlo + o1) = lo;
        }
    }
}

// ---------------------------------------------------------------------------
extern "C" void kernel_launch(void* const* d_in, const int* in_sizes, int n_in,
                              void* d_out, int out_size) {
    const float* x  = (const float*)d_in[0];
    const float* Wq = (const float*)d_in[1];
    const float* Wk = (const float*)d_in[2];
    const float* Wv = (const float*)d_in[3];
    const float* Wp = (const float*)d_in[4];
    const float* bp = (const float*)d_in[5];
    float* out = (float*)d_out;

    prep<<<(XW + WTW + WPW) / 256, 256>>>(x, Wq, Wk, Wv, Wp);

    const int gsmem = 8 * TILE_B + 32;   // 2 buffers x 4 tiles + 4 mbarriers
    cudaFuncSetAttribute(gemm_tc<0>, cudaFuncAttributeMaxDynamicSharedMemorySize, gsmem);
    cudaFuncSetAttribute(gemm_tc<1>, cudaFuncAttributeMaxDynamicSharedMemorySize, gsmem);

    gemm_tc<0><<<dim3(NQKV/128, BT/128), 256, gsmem>>>(nullptr, nullptr);

    cudaFuncSetAttribute(attn_flash, cudaFuncAttributeMaxDynamicSharedMemorySize, ASZ + 16);
    attn_flash<<<BB*HH, 256, ASZ + 16>>>();

    gemm_tc<1><<<dim3(CC/128, BT/128), 256, gsmem>>>(bp, out);
}

// round 11
// speedup vs baseline: 1.4002x; 1.4002x over previous
#include <cuda_runtime.h>
#include <cuda_fp16.h>
#include <cstdint>

#define BB 64
#define TT 256
#define CC 384
#define HH 6
#define DD 64
#define BT (BB*TT)         // 16384
#define NQKV (3*HH*DD)     // 1152
#define PITCH 40           // fp16 elems per smem/gmem tile row
#define TILE_E 5120        // elems per 128x32 tile
#define TILE_B 10240       // bytes per tile
#define NCH 12             // K chunks (384/32)

// prep work partition (8 elems per thread)
#define XW (BT*CC/8)       // 786432
#define WTW (NQKV*CC/8)    // 55296
#define WPW (CC*CC/8)      // 18432

// attention smem layout (bytes). Q/K pitch 72 fp16 (144B), Vt pitch 264 fp16 (528B)
#define AQH 0
#define AQL 36864
#define AKH 73728
#define AVH 110592
#define ASZ 144384

// ---------------- static scratch (tiled/pitched fp16 layouts) ----------------
__device__ __align__(128) __half g_Xhi[(size_t)128*NCH*TILE_E], g_Xlo[(size_t)128*NCH*TILE_E];
__device__ __align__(128) __half g_Wth[(size_t)9*NCH*TILE_E];
__device__ __align__(128) __half g_Ath[(size_t)128*NCH*TILE_E], g_Atl[(size_t)128*NCH*TILE_E];
__device__ __align__(128) __half g_Wph[(size_t)3*NCH*TILE_E];
__device__ __align__(128) __half g_Qh[(size_t)BB*HH*TT*72], g_Ql[(size_t)BB*HH*TT*72];
__device__ __align__(128) __half g_Kh[(size_t)BB*HH*TT*72];
__device__ __align__(128) __half g_Vth[(size_t)BB*HH*DD*264];

// ---------------- helpers ----------------
__device__ __forceinline__ void bulk_g2s(uint32_t dst, const void* src, uint32_t bytes,
                                         uint32_t mbar) {
    asm volatile("cp.async.bulk.shared::cluster.global.mbarrier::complete_tx::bytes "
                 "[%0], [%1], %2, [%3];"
                 :: "r"(dst), "l"(src), "r"(bytes), "r"(mbar) : "memory");
}
__device__ __forceinline__ void mbar_init(uint32_t mbar, uint32_t cnt) {
    asm volatile("mbarrier.init.shared.b64 [%0], %1;" :: "r"(mbar), "r"(cnt) : "memory");
}
__device__ __forceinline__ void mbar_expect(uint32_t mbar, uint32_t bytes) {
    asm volatile("mbarrier.arrive.expect_tx.shared.b64 _, [%0], %1;"
                 :: "r"(mbar), "r"(bytes) : "memory");
}
__device__ __forceinline__ void mbar_arrive(uint32_t mbar) {
    asm volatile("mbarrier.arrive.shared.b64 _, [%0];" :: "r"(mbar) : "memory");
}
__device__ __forceinline__ void mbar_wait(uint32_t mbar, uint32_t parity) {
    asm volatile("{\n\t.reg .pred P;\n\t"
                 "WL_%=:\n\t"
                 "mbarrier.try_wait.parity.acquire.cta.shared::cta.b64 P, [%0], %1, 0x989680;\n\t"
                 "@P bra WD_%=;\n\t"
                 "bra WL_%=;\n\t"
                 "WD_%=:\n\t}"
                 :: "r"(mbar), "r"(parity) : "memory");
}
__device__ __forceinline__ void fence_async() {
    asm volatile("fence.proxy.async.shared::cta;" ::: "memory");
}
__device__ __forceinline__ void mma_f16(float* c, const uint32_t* a, const uint32_t* b) {
    asm volatile("mma.sync.aligned.m16n8k16.row.col.f32.f16.f16.f32 "
                 "{%0,%1,%2,%3}, {%4,%5,%6,%7}, {%8,%9}, {%0,%1,%2,%3};"
                 : "+f"(c[0]), "+f"(c[1]), "+f"(c[2]), "+f"(c[3])
                 : "r"(a[0]), "r"(a[1]), "r"(a[2]), "r"(a[3]),
                   "r"(b[0]), "r"(b[1]));
}
__device__ __forceinline__ void ldm_x4(uint32_t* r, uint32_t addr) {
    asm volatile("ldmatrix.sync.aligned.m8n8.x4.shared.b16 {%0,%1,%2,%3}, [%4];"
                 : "=r"(r[0]), "=r"(r[1]), "=r"(r[2]), "=r"(r[3]) : "r"(addr));
}
__device__ __forceinline__ uint32_t packh2(float x, float y) {
    __half hx = __float2half_rn(x), hy = __float2half_rn(y);
    uint16_t ux = *(uint16_t*)&hx, uy = *(uint16_t*)&hy;
    return (uint32_t)ux | ((uint32_t)uy << 16);
}
__device__ __forceinline__ void split2(float x, float y, uint32_t& hi, uint32_t& lo) {
    __half hx = __float2half_rn(x), hy = __float2half_rn(y);
    __half lx = __float2half_rn(x - __half2float(hx));
    __half ly = __float2half_rn(y - __half2float(hy));
    uint16_t uhx = *(uint16_t*)&hx, uhy = *(uint16_t*)&hy;
    uint16_t ulx = *(uint16_t*)&lx, uly = *(uint16_t*)&ly;
    hi = (uint32_t)uhx | ((uint32_t)uhy << 16);
    lo = (uint32_t)ulx | ((uint32_t)uly << 16);
}
__device__ __forceinline__ size_t tiled_idx(int m, int k) {
    return ((size_t)(m >> 7) * NCH + (k >> 5)) * TILE_E + (m & 127) * PITCH + (k & 31);
}

// ---------------- fused prep: split X (hi/lo), pack Wt (single), Wp (single) ----------------
__global__ void prep(const float* __restrict__ x,
                     const float* __restrict__ Wq, const float* __restrict__ Wk,
                     const float* __restrict__ Wv, const float* __restrict__ Wp) {
    int g = blockIdx.x * blockDim.x + threadIdx.x;
    if (g < XW) {
        int i = g * 8;
        int m = i / CC, k = i % CC;
        float4 v0 = *(const float4*)(x + i);
        float4 v1 = *(const float4*)(x + i + 4);
        __half h[8], l[8];
        float vv[8] = {v0.x,v0.y,v0.z,v0.w,v1.x,v1.y,v1.z,v1.w};
        #pragma unroll
        for (int j = 0; j < 8; j++) {
            h[j] = __float2half_rn(vv[j]);
            l[j] = __float2half_rn(vv[j] - __half2float(h[j]));
        }
        size_t d = tiled_idx(m, k);
        *(uint4*)(g_Xhi + d) = *(uint4*)h;
        *(uint4*)(g_Xlo + d) = *(uint4*)l;
    } else if (g < XW + WTW) {
        int idx8 = g - XW;
        int n = idx8 / (CC/8), c0 = (idx8 % (CC/8)) * 8;
        int proj = n / (HH * DD), r = n % (HH * DD);
        int h = r / DD, d = r % DD;
        const float* W = (proj == 0) ? Wq : (proj == 1) ? Wk : Wv;
        size_t o = tiled_idx(n, c0);
        #pragma unroll
        for (int cc = 0; cc < 8; cc++)
            g_Wth[o + cc] = __float2half_rn(W[((size_t)h * CC + c0 + cc) * DD + d]);
    } else if (g < XW + WTW + WPW) {
        int i = (g - XW - WTW) * 8;
        int n = i / CC, k = i % CC;
        float4 v0 = *(const float4*)(Wp + i);
        float4 v1 = *(const float4*)(Wp + i + 4);
        __half h[8];
        float vv[8] = {v0.x,v0.y,v0.z,v0.w,v1.x,v1.y,v1.z,v1.w};
        #pragma unroll
        for (int j = 0; j < 8; j++) h[j] = __float2half_rn(vv[j]);
        size_t d = tiled_idx(n, k);
        *(uint4*)(g_Wph + d) = *(uint4*)h;
    }
}

// ---------------------------------------------------------------------------
// HMMA GEMM, 2-product: D = (Ah+Al)*B (A split fp16 hi/lo, B single fp16).
// Bulk staging (3 tiles/stage), ldmatrix frags, async buffer recycle.
// MODE 0: A=X, B=Wt; emit Q hi/lo, K single (pitch 72), Vt single (pitch 264).
// MODE 1: A=att, B=Wp; +bias -> fp32 out.
// ---------------------------------------------------------------------------
template<int MODE>
__global__ __launch_bounds__(256, 2) void gemm_tc(const float* __restrict__ bp,
                                                  float* __restrict__ outp) {
    extern __shared__ __align__(128) char sm[];
    const __half* Ahi = (MODE == 0) ? g_Xhi : g_Ath;
    const __half* Alo = (MODE == 0) ? g_Xlo : g_Atl;
    const __half* Bs  = (MODE == 0) ? g_Wth : g_Wph;

    const int tid = threadIdx.x, lane = tid & 31, wid = tid >> 5;
    const int wm = wid & 3, wn = wid >> 2;
    const int lr = lane >> 2, lc = lane & 3;
    const int rb = blockIdx.y, cb = blockIdx.x;
    const int row0 = rb * 128, col0 = cb * 128;
    const uint32_t sbase = (uint32_t)__cvta_generic_to_shared(sm);
    const uint32_t fullb0  = sbase + 6*TILE_B,  fullb1  = fullb0 + 8;
    const uint32_t emptyb0 = fullb0 + 16,       emptyb1 = fullb0 + 24;

    uint32_t aoff[2];
    #pragma unroll
    for (int mt = 0; mt < 2; mt++)
        aoff[mt] = (uint32_t)(wm*32 + mt*16 + (lane & 15)) * PITCH + ((lane >> 4) & 1) * 8;
    uint32_t boff[4];
    #pragma unroll
    for (int jj = 0; jj < 4; jj++)
        boff[jj] = (uint32_t)(wn*64 + jj*16 + ((lane >> 4) & 1)*8 + (lane & 7)) * PITCH
                   + ((lane >> 3) & 1) * 8;

    if (tid == 0) {
        mbar_init(fullb0, 1);  mbar_init(fullb1, 1);
        mbar_init(emptyb0, 8); mbar_init(emptyb1, 8);
    }
    __syncthreads();

    auto issue = [&](int buf, int c) {
        uint32_t st = sbase + buf * 3 * TILE_B;
        uint32_t mb = buf ? fullb1 : fullb0;
        fence_async();
        mbar_expect(mb, 3 * TILE_B);
        bulk_g2s(st + 0*TILE_B, Ahi + ((size_t)rb*NCH + c)*TILE_E, TILE_B, mb);
        bulk_g2s(st + 1*TILE_B, Alo + ((size_t)rb*NCH + c)*TILE_E, TILE_B, mb);
        bulk_g2s(st + 2*TILE_B, Bs  + ((size_t)cb*NCH + c)*TILE_E, TILE_B, mb);
    };

    float acc[2][8][4];
    #pragma unroll
    for (int i = 0; i < 2; i++)
        #pragma unroll
        for (int j = 0; j < 8; j++)
            #pragma unroll
            for (int r = 0; r < 4; r++) acc[i][j][r] = 0.f;

    if (tid == 0) { issue(0, 0); issue(1, 1); }

    for (int kc = 0; kc < NCH; kc++) {
        int buf = kc & 1;
        mbar_wait(buf ? fullb1 : fullb0, (kc >> 1) & 1);

        const uint32_t sbuf = sbase + buf * 3 * TILE_B;
        #pragma unroll
        for (int ks = 0; ks < 2; ks++) {
            const uint32_t kb = ks * 16;
            uint32_t ah[2][4], al[2][4];
            #pragma unroll
            for (int mt = 0; mt < 2; mt++) {
                uint32_t ad = sbuf + (aoff[mt] + kb) * 2;
                ldm_x4(ah[mt], ad);
                ldm_x4(al[mt], ad + TILE_B);
            }
            #pragma unroll
            for (int jj = 0; jj < 4; jj++) {
                uint32_t bd = sbuf + 2*TILE_B + (boff[jj] + kb) * 2;
                uint32_t bh4[4];
                ldm_x4(bh4, bd);
                #pragma unroll
                for (int mt = 0; mt < 2; mt++) {
                    mma_f16(acc[mt][2*jj],   ah[mt], bh4);
                    mma_f16(acc[mt][2*jj],   al[mt], bh4);
                    mma_f16(acc[mt][2*jj+1], ah[mt], bh4 + 2);
                    mma_f16(acc[mt][2*jj+1], al[mt], bh4 + 2);
                }
            }
        }
        if (lane == 0) mbar_arrive(buf ? emptyb1 : emptyb0);
        if (tid == 0 && kc + 2 < NCH) {
            mbar_wait(buf ? emptyb1 : emptyb0, (kc >> 1) & 1);
            issue(buf, kc + 2);
        }
    }

    // epilogue
    #pragma unroll
    for (int i = 0; i < 2; i++) {
        int m0 = row0 + wm*32 + i*16 + lr;
        #pragma unroll
        for (int j = 0; j < 8; j++) {
            int nn = col0 + wn*64 + j*8 + lc*2;
            if (MODE == 0) {
                int proj = nn / (HH*DD);
                int rem  = nn % (HH*DD);
                int h = rem / DD, d = rem % DD;
                int b = m0 / TT, t = m0 % TT;
                int bh = b*HH + h;
                if (proj == 0) {           // Q: hi/lo (exact storage)
                    uint32_t h01, l01, h23, l23;
                    split2(acc[i][j][0], acc[i][j][1], h01, l01);
                    split2(acc[i][j][2], acc[i][j][3], h23, l23);
                    size_t o = ((size_t)bh*TT + t)*72 + d;
                    *(uint32_t*)(g_Qh + o) = h01;          *(uint32_t*)(g_Ql + o) = l01;
                    *(uint32_t*)(g_Qh + o + 8*72) = h23;   *(uint32_t*)(g_Ql + o + 8*72) = l23;
                } else if (proj == 1) {    // K: single fp16
                    size_t o = ((size_t)bh*TT + t)*72 + d;
                    *(uint32_t*)(g_Kh + o)        = packh2(acc[i][j][0], acc[i][j][1]);
                    *(uint32_t*)(g_Kh + o + 8*72) = packh2(acc[i][j][2], acc[i][j][3]);
                } else {                   // V: single fp16, transposed
                    size_t o = ((size_t)bh*DD + d)*264 + t;
                    g_Vth[o]           = __float2half_rn(acc[i][j][0]);
                    g_Vth[o + 264]     = __float2half_rn(acc[i][j][1]);
                    g_Vth[o + 8]       = __float2half_rn(acc[i][j][2]);
                    g_Vth[o + 264 + 8] = __float2half_rn(acc[i][j][3]);
                }
            } else {
                float2 bb = *(const float2*)(bp + nn);
                *(float2*)(outp + (size_t)m0 * CC + nn) =
                    make_float2(acc[i][j][0] + bb.x, acc[i][j][1] + bb.y);
                *(float2*)(outp + (size_t)(m0 + 8) * CC + nn) =
                    make_float2(acc[i][j][2] + bb.x, acc[i][j][3] + bb.y);
            }
        }
    }
}

// ---------------------------------------------------------------------------
// HMMA flash attention, 2-product fp16: S = (Qh+Ql)*K, O += (Ph+Pl)*V.
// Load-balanced 16-row tiles (j=w and j=15-w -> exactly 5 tile-chunks/warp).
// ---------------------------------------------------------------------------
__global__ __launch_bounds__(256, 1) void attn_flash() {
    extern __shared__ __align__(128) char sma[];
    const int bh = blockIdx.x;
    const int tid = threadIdx.x, lane = tid & 31, w = tid >> 5;
    const int lr = lane >> 2, lc = lane & 3;
    const uint32_t sb = (uint32_t)__cvta_generic_to_shared(sma);
    const uint32_t mb = sb + ASZ;

    if (tid == 0) {
        mbar_init(mb, 1);
        fence_async();
        mbar_expect(mb, ASZ);
        bulk_g2s(sb + AQH, g_Qh  + (size_t)bh*TT*72,  36864, mb);
        bulk_g2s(sb + AQL, g_Ql  + (size_t)bh*TT*72,  36864, mb);
        bulk_g2s(sb + AKH, g_Kh  + (size_t)bh*TT*72,  36864, mb);
        bulk_g2s(sb + AVH, g_Vth + (size_t)bh*DD*264, 33792, mb);
    }
    __syncthreads();
    mbar_wait(mb, 0);

    const int b = bh / HH, h = bh % HH;

    #pragma unroll
    for (int half = 0; half < 2; half++) {
        const int jt = half ? (15 - w) : w;
        const int rowbase = jt * 16;
        const int cnt = (jt >> 2) + 1;
        const int diagc = jt >> 2;

        uint32_t qh[4][4], ql[4][4];
        #pragma unroll
        for (int ks = 0; ks < 4; ks++) {
            uint32_t off = (uint32_t)(rowbase + lr)*144 + (ks*16 + lc*2)*2;
            qh[ks][0] = *(const uint32_t*)(sma + AQH + off);
            qh[ks][1] = *(const uint32_t*)(sma + AQH + off + 8*144);
            qh[ks][2] = *(const uint32_t*)(sma + AQH + off + 16);
            qh[ks][3] = *(const uint32_t*)(sma + AQH + off + 8*144 + 16);
            ql[ks][0] = *(const uint32_t*)(sma + AQL + off);
            ql[ks][1] = *(const uint32_t*)(sma + AQL + off + 8*144);
            ql[ks][2] = *(const uint32_t*)(sma + AQL + off + 16);
            ql[ks][3] = *(const uint32_t*)(sma + AQL + off + 8*144 + 16);
        }

        float O[8][4];
        #pragma unroll
        for (int j = 0; j < 8; j++)
            #pragma unroll
            for (int r = 0; r < 4; r++) O[j][r] = 0.f;
        float rowm[2] = {-1e30f, -1e30f};
        float rowl[2] = {0.f, 0.f};

        for (int c = 0; c < cnt; c++) {
            const int s0 = c * 64;
            float S[8][4];
            #pragma unroll
            for (int n = 0; n < 8; n++)
                #pragma unroll
                for (int r = 0; r < 4; r++) S[n][r] = 0.f;

            #pragma unroll
            for (int ks = 0; ks < 4; ks++) {
                #pragma unroll
                for (int n = 0; n < 8; n++) {
                    uint32_t off = (uint32_t)(s0 + n*8 + lr)*144 + (ks*16 + lc*2)*2;
                    uint32_t kb2[2];
                    kb2[0] = *(const uint32_t*)(sma + AKH + off);
                    kb2[1] = *(const uint32_t*)(sma + AKH + off + 16);
                    mma_f16(S[n], qh[ks], kb2);
                    mma_f16(S[n], ql[ks], kb2);
                }
            }

            const bool diag = (c == diagc);
            const int trow = rowbase + lr;
            #pragma unroll
            for (int n = 0; n < 8; n++) {
                int scol = s0 + n*8 + lc*2;
                S[n][0] *= 0.125f; S[n][1] *= 0.125f;
                S[n][2] *= 0.125f; S[n][3] *= 0.125f;
                if (diag) {
                    if (scol     > trow)     S[n][0] = -1e30f;
                    if (scol + 1 > trow)     S[n][1] = -1e30f;
                    if (scol     > trow + 8) S[n][2] = -1e30f;
                    if (scol + 1 > trow + 8) S[n][3] = -1e30f;
                }
            }

            #pragma unroll
            for (int rg = 0; rg < 2; rg++) {
                float cm = -1e30f;
                #pragma unroll
                for (int n = 0; n < 8; n++) {
                    cm = fmaxf(cm, S[n][rg*2]);
                    cm = fmaxf(cm, S[n][rg*2+1]);
                }
                cm = fmaxf(cm, __shfl_xor_sync(0xffffffffu, cm, 1));
                cm = fmaxf(cm, __shfl_xor_sync(0xffffffffu, cm, 2));
                float mold = rowm[rg];
                float mn = fmaxf(mold, cm);
                float alpha = __expf(mold - mn);
                rowm[rg] = mn;
                float ls = 0.f;
                #pragma unroll
                for (int n = 0; n < 8; n++) {
                    float p0 = __expf(S[n][rg*2]   - mn);
                    float p1 = __expf(S[n][rg*2+1] - mn);
                    S[n][rg*2] = p0; S[n][rg*2+1] = p1;
                    ls += p0 + p1;
                }
                rowl[rg] = rowl[rg]*alpha + ls;
                #pragma unroll
                for (int j = 0; j < 8; j++) {
                    O[j][rg*2]   *= alpha;
                    O[j][rg*2+1] *= alpha;
                }
            }

            #pragma unroll
            for (int ks2 = 0; ks2 < 4; ks2++) {
                uint32_t ph[4], pl[4];
                split2(S[2*ks2][0],   S[2*ks2][1],   ph[0], pl[0]);
                split2(S[2*ks2][2],   S[2*ks2][3],   ph[1], pl[1]);
                split2(S[2*ks2+1][0], S[2*ks2+1][1], ph[2], pl[2]);
                split2(S[2*ks2+1][2], S[2*ks2+1][3], ph[3], pl[3]);
                #pragma unroll
                for (int j = 0; j < 8; j++) {
                    uint32_t off = (uint32_t)(j*8 + lr)*528 + (s0 + ks2*16 + lc*2)*2;
                    uint32_t vb2[2];
                    vb2[0] = *(const uint32_t*)(sma + AVH + off);
                    vb2[1] = *(const uint32_t*)(sma + AVH + off + 16);
                    mma_f16(O[j], ph, vb2);
                    mma_f16(O[j], pl, vb2);
                }
            }
        }

        float linv0, linv1;
        {
            float lf = rowl[0];
            lf += __shfl_xor_sync(0xffffffffu, lf, 1);
            lf += __shfl_xor_sync(0xffffffffu, lf, 2);
            linv0 = 1.f / lf;
            lf = rowl[1];
            lf += __shfl_xor_sync(0xffffffffu, lf, 1);
            lf += __shfl_xor_sync(0xffffffffu, lf, 2);
            linv1 = 1.f / lf;
        }
        const int gm0 = b*TT + rowbase + lr;
        #pragma unroll
        for (int j = 0; j < 8; j++) {
            int n = h*DD + j*8 + lc*2;
            uint32_t hi, lo;
            size_t o0 = tiled_idx(gm0, n);
            split2(O[j][0]*linv0, O[j][1]*linv0, hi, lo);
            *(uint32_t*)(g_Ath + o0) = hi;  *(uint32_t*)(g_Atl + o0) = lo;
            size_t o1 = tiled_idx(gm0 + 8, n);
            split2(O[j][2]*linv1, O[j][3]*linv1, hi, lo);
            *(uint32_t*)(g_Ath + o1) = hi;  *(uint32_t*)(g_Atl + o1) = lo;
        }
    }
}

// ---------------------------------------------------------------------------
extern "C" void kernel_launch(void* const* d_in, const int* in_sizes, int n_in,
                              void* d_out, int out_size) {
    const float* x  = (const float*)d_in[0];
    const float* Wq = (const float*)d_in[1];
    const float* Wk = (const float*)d_in[2];
    const float* Wv = (const float*)d_in[3];
    const float* Wp = (const float*)d_in[4];
    const float* bp = (const float*)d_in[5];
    float* out = (float*)d_out;

    prep<<<(XW + WTW + WPW) / 256, 256>>>(x, Wq, Wk, Wv, Wp);

    const int gsmem = 6 * TILE_B + 32;   // 2 buffers x 3 tiles + 4 mbarriers
    cudaFuncSetAttribute(gemm_tc<0>, cudaFuncAttributeMaxDynamicSharedMemorySize, gsmem);
    cudaFuncSetAttribute(gemm_tc<1>, cudaFuncAttributeMaxDynamicSharedMemorySize, gsmem);

    gemm_tc<0><<<dim3(NQKV/128, BT/128), 256, gsmem>>>(nullptr, nullptr);

    cudaFuncSetAttribute(attn_flash, cudaFuncAttributeMaxDynamicSharedMemorySize, ASZ + 16);
    attn_flash<<<BB*HH, 256, ASZ + 16>>>();

    gemm_tc<1><<<dim3(CC/128, BT/128), 256, gsmem>>>(bp, out);
}

// round 12
// speedup vs baseline: 1.5941x; 1.1385x over previous
#include <cuda_runtime.h>
#include <cuda_fp16.h>
#include <cstdint>

#define BB 64
#define TT 256
#define CC 384
#define HH 6
#define DD 64
#define BT (BB*TT)         // 16384
#define NQKV (3*HH*DD)     // 1152
#define PITCH 40           // fp16 elems per smem/gmem tile row
#define TILE_E 5120        // elems per 128x32 tile
#define TILE_B 10240       // bytes per tile
#define NCH 12             // K chunks (384/32)
#define NSTAGE 3

// prep work partition (8 elems per thread)
#define XW (BT*CC/8)       // 786432
#define WTW (NQKV*CC/8)    // 55296
#define WPW (CC*CC/8)      // 18432

// attention smem layout (bytes). Q/K pitch 72 fp16 (144B), Vt pitch 264 fp16 (528B)
#define AQH 0
#define AQL 36864
#define AKH 73728
#define AVH 110592
#define ASZ 144384

// ---------------- static scratch (tiled/pitched fp16 layouts) ----------------
__device__ __align__(128) __half g_Xhi[(size_t)128*NCH*TILE_E], g_Xlo[(size_t)128*NCH*TILE_E];
__device__ __align__(128) __half g_Wth[(size_t)9*NCH*TILE_E];
__device__ __align__(128) __half g_Ath[(size_t)128*NCH*TILE_E];
__device__ __align__(128) __half g_Wph[(size_t)3*NCH*TILE_E];
__device__ __align__(128) __half g_Qh[(size_t)BB*HH*TT*72], g_Ql[(size_t)BB*HH*TT*72];
__device__ __align__(128) __half g_Kh[(size_t)BB*HH*TT*72];
__device__ __align__(128) __half g_Vth[(size_t)BB*HH*DD*264];

// ---------------- helpers ----------------
__device__ __forceinline__ void bulk_g2s(uint32_t dst, const void* src, uint32_t bytes,
                                         uint32_t mbar) {
    asm volatile("cp.async.bulk.shared::cluster.global.mbarrier::complete_tx::bytes "
                 "[%0], [%1], %2, [%3];"
                 :: "r"(dst), "l"(src), "r"(bytes), "r"(mbar) : "memory");
}
__device__ __forceinline__ void mbar_init(uint32_t mbar, uint32_t cnt) {
    asm volatile("mbarrier.init.shared.b64 [%0], %1;" :: "r"(mbar), "r"(cnt) : "memory");
}
__device__ __forceinline__ void mbar_expect(uint32_t mbar, uint32_t bytes) {
    asm volatile("mbarrier.arrive.expect_tx.shared.b64 _, [%0], %1;"
                 :: "r"(mbar), "r"(bytes) : "memory");
}
__device__ __forceinline__ void mbar_arrive(uint32_t mbar) {
    asm volatile("mbarrier.arrive.shared.b64 _, [%0];" :: "r"(mbar) : "memory");
}
__device__ __forceinline__ void mbar_wait(uint32_t mbar, uint32_t parity) {
    asm volatile("{\n\t.reg .pred P;\n\t"
                 "WL_%=:\n\t"
                 "mbarrier.try_wait.parity.acquire.cta.shared::cta.b64 P, [%0], %1, 0x989680;\n\t"
                 "@P bra WD_%=;\n\t"
                 "bra WL_%=;\n\t"
                 "WD_%=:\n\t}"
                 :: "r"(mbar), "r"(parity) : "memory");
}
__device__ __forceinline__ void fence_async() {
    asm volatile("fence.proxy.async.shared::cta;" ::: "memory");
}
__device__ __forceinline__ void mma_f16(float* c, const uint32_t* a, const uint32_t* b) {
    asm volatile("mma.sync.aligned.m16n8k16.row.col.f32.f16.f16.f32 "
                 "{%0,%1,%2,%3}, {%4,%5,%6,%7}, {%8,%9}, {%0,%1,%2,%3};"
                 : "+f"(c[0]), "+f"(c[1]), "+f"(c[2]), "+f"(c[3])
                 : "r"(a[0]), "r"(a[1]), "r"(a[2]), "r"(a[3]),
                   "r"(b[0]), "r"(b[1]));
}
__device__ __forceinline__ void ldm_x4(uint32_t* r, uint32_t addr) {
    asm volatile("ldmatrix.sync.aligned.m8n8.x4.shared.b16 {%0,%1,%2,%3}, [%4];"
                 : "=r"(r[0]), "=r"(r[1]), "=r"(r[2]), "=r"(r[3]) : "r"(addr));
}
__device__ __forceinline__ uint32_t packh2(float x, float y) {
    __half hx = __float2half_rn(x), hy = __float2half_rn(y);
    uint16_t ux = *(uint16_t*)&hx, uy = *(uint16_t*)&hy;
    return (uint32_t)ux | ((uint32_t)uy << 16);
}
__device__ __forceinline__ void split2(float x, float y, uint32_t& hi, uint32_t& lo) {
    __half hx = __float2half_rn(x), hy = __float2half_rn(y);
    __half lx = __float2half_rn(x - __half2float(hx));
    __half ly = __float2half_rn(y - __half2float(hy));
    uint16_t uhx = *(uint16_t*)&hx, uhy = *(uint16_t*)&hy;
    uint16_t ulx = *(uint16_t*)&lx, uly = *(uint16_t*)&ly;
    hi = (uint32_t)uhx | ((uint32_t)uhy << 16);
    lo = (uint32_t)ulx | ((uint32_t)uly << 16);
}
__device__ __forceinline__ size_t tiled_idx(int m, int k) {
    return ((size_t)(m >> 7) * NCH + (k >> 5)) * TILE_E + (m & 127) * PITCH + (k & 31);
}

// ---------------- fused prep ----------------
__global__ void prep(const float* __restrict__ x,
                     const float* __restrict__ Wq, const float* __restrict__ Wk,
                     const float* __restrict__ Wv, const float* __restrict__ Wp) {
    int g = blockIdx.x * blockDim.x + threadIdx.x;
    if (g < XW) {
        int i = g * 8;
        int m = i / CC, k = i % CC;
        float4 v0 = *(const float4*)(x + i);
        float4 v1 = *(const float4*)(x + i + 4);
        __half h[8], l[8];
        float vv[8] = {v0.x,v0.y,v0.z,v0.w,v1.x,v1.y,v1.z,v1.w};
        #pragma unroll
        for (int j = 0; j < 8; j++) {
            h[j] = __float2half_rn(vv[j]);
            l[j] = __float2half_rn(vv[j] - __half2float(h[j]));
        }
        size_t d = tiled_idx(m, k);
        *(uint4*)(g_Xhi + d) = *(uint4*)h;
        *(uint4*)(g_Xlo + d) = *(uint4*)l;
    } else if (g < XW + WTW) {
        int idx8 = g - XW;
        int n = idx8 / (CC/8), c0 = (idx8 % (CC/8)) * 8;
        int proj = n / (HH * DD), r = n % (HH * DD);
        int h = r / DD, d = r % DD;
        const float* W = (proj == 0) ? Wq : (proj == 1) ? Wk : Wv;
        size_t o = tiled_idx(n, c0);
        #pragma unroll
        for (int cc = 0; cc < 8; cc++)
            g_Wth[o + cc] = __float2half_rn(W[((size_t)h * CC + c0 + cc) * DD + d]);
    } else if (g < XW + WTW + WPW) {
        int i = (g - XW - WTW) * 8;
        int n = i / CC, k = i % CC;
        float4 v0 = *(const float4*)(Wp + i);
        float4 v1 = *(const float4*)(Wp + i + 4);
        __half h[8];
        float vv[8] = {v0.x,v0.y,v0.z,v0.w,v1.x,v1.y,v1.z,v1.w};
        #pragma unroll
        for (int j = 0; j < 8; j++) h[j] = __float2half_rn(vv[j]);
        size_t d = tiled_idx(n, k);
        *(uint4*)(g_Wph + d) = *(uint4*)h;
    }
}

// ---------------------------------------------------------------------------
// HMMA GEMM, 3-stage bulk pipeline.
// MODE 0: A = X hi/lo (2 products), B = Wt; emit Q hi/lo, K, Vt.
// MODE 1: A = att single (1 product), B = Wp; +bias -> fp32 out.
// ---------------------------------------------------------------------------
template<int MODE>
__global__ __launch_bounds__(256, 2) void gemm_tc(const float* __restrict__ bp,
                                                  float* __restrict__ outp) {
    constexpr int NA = (MODE == 0) ? 2 : 1;   // A tiles per stage
    constexpr int NT = NA + 1;                // total tiles per stage
    extern __shared__ __align__(128) char sm[];
    const __half* Ahi = (MODE == 0) ? g_Xhi : g_Ath;
    const __half* Bs  = (MODE == 0) ? g_Wth : g_Wph;

    const int tid = threadIdx.x, lane = tid & 31, wid = tid >> 5;
    const int wm = wid & 3, wn = wid >> 2;
    const int lr = lane >> 2, lc = lane & 3;
    const int rb = blockIdx.y, cb = blockIdx.x;
    const int row0 = rb * 128, col0 = cb * 128;
    const uint32_t sbase = (uint32_t)__cvta_generic_to_shared(sm);
    const uint32_t barb = sbase + NSTAGE * NT * TILE_B;   // full[3] then empty[3]

    uint32_t aoff[2];
    #pragma unroll
    for (int mt = 0; mt < 2; mt++)
        aoff[mt] = (uint32_t)(wm*32 + mt*16 + (lane & 15)) * PITCH + ((lane >> 4) & 1) * 8;
    uint32_t boff[4];
    #pragma unroll
    for (int jj = 0; jj < 4; jj++)
        boff[jj] = (uint32_t)(wn*64 + jj*16 + ((lane >> 4) & 1)*8 + (lane & 7)) * PITCH
                   + ((lane >> 3) & 1) * 8;

    if (tid == 0) {
        #pragma unroll
        for (int s = 0; s < NSTAGE; s++) {
            mbar_init(barb + s*8, 1);                 // full
            mbar_init(barb + (NSTAGE + s)*8, 8);      // empty (8 warp arrivals)
        }
    }
    __syncthreads();

    auto issue = [&](int s, int c) {
        uint32_t st = sbase + s * NT * TILE_B;
        uint32_t mb = barb + s*8;
        fence_async();
        mbar_expect(mb, NT * TILE_B);
        bulk_g2s(st, Ahi + ((size_t)rb*NCH + c)*TILE_E, TILE_B, mb);
        if (MODE == 0)
            bulk_g2s(st + TILE_B, g_Xlo + ((size_t)rb*NCH + c)*TILE_E, TILE_B, mb);
        bulk_g2s(st + NA*TILE_B, Bs + ((size_t)cb*NCH + c)*TILE_E, TILE_B, mb);
    };

    float acc[2][8][4];
    #pragma unroll
    for (int i = 0; i < 2; i++)
        #pragma unroll
        for (int j = 0; j < 8; j++)
            #pragma unroll
            for (int r = 0; r < 4; r++) acc[i][j][r] = 0.f;

    if (tid == 0) { issue(0, 0); issue(1, 1); issue(2, 2); }

    for (int kc = 0; kc < NCH; kc++) {
        int buf = kc % NSTAGE;
        int par = (kc / NSTAGE) & 1;
        mbar_wait(barb + buf*8, par);

        const uint32_t sbuf = sbase + buf * NT * TILE_B;
        #pragma unroll
        for (int ks = 0; ks < 2; ks++) {
            const uint32_t kb = ks * 16;
            uint32_t ah[2][4], al[2][4];
            #pragma unroll
            for (int mt = 0; mt < 2; mt++) {
                uint32_t ad = sbuf + (aoff[mt] + kb) * 2;
                ldm_x4(ah[mt], ad);
                if (MODE == 0) ldm_x4(al[mt], ad + TILE_B);
            }
            #pragma unroll
            for (int jj = 0; jj < 4; jj++) {
                uint32_t bd = sbuf + NA*TILE_B + (boff[jj] + kb) * 2;
                uint32_t bh4[4];
                ldm_x4(bh4, bd);
                #pragma unroll
                for (int mt = 0; mt < 2; mt++) {
                    mma_f16(acc[mt][2*jj],   ah[mt], bh4);
                    mma_f16(acc[mt][2*jj+1], ah[mt], bh4 + 2);
                    if (MODE == 0) {
                        mma_f16(acc[mt][2*jj],   al[mt], bh4);
                        mma_f16(acc[mt][2*jj+1], al[mt], bh4 + 2);
                    }
                }
            }
        }
        if (lane == 0) mbar_arrive(barb + (NSTAGE + buf)*8);
        if (tid == 0 && kc + NSTAGE < NCH) {
            mbar_wait(barb + (NSTAGE + buf)*8, par);
            issue(buf, kc + NSTAGE);
        }
    }

    // epilogue
    #pragma unroll
    for (int i = 0; i < 2; i++) {
        int m0 = row0 + wm*32 + i*16 + lr;
        #pragma unroll
        for (int j = 0; j < 8; j++) {
            int nn = col0 + wn*64 + j*8 + lc*2;
            if (MODE == 0) {
                int proj = nn / (HH*DD);
                int rem  = nn % (HH*DD);
                int h = rem / DD, d = rem % DD;
                int b = m0 / TT, t = m0 % TT;
                int bh = b*HH + h;
                if (proj == 0) {           // Q: hi/lo (protect score path)
                    uint32_t h01, l01, h23, l23;
                    split2(acc[i][j][0], acc[i][j][1], h01, l01);
                    split2(acc[i][j][2], acc[i][j][3], h23, l23);
                    size_t o = ((size_t)bh*TT + t)*72 + d;
                    *(uint32_t*)(g_Qh + o) = h01;          *(uint32_t*)(g_Ql + o) = l01;
                    *(uint32_t*)(g_Qh + o + 8*72) = h23;   *(uint32_t*)(g_Ql + o + 8*72) = l23;
                } else if (proj == 1) {    // K: single fp16
                    size_t o = ((size_t)bh*TT + t)*72 + d;
                    *(uint32_t*)(g_Kh + o)        = packh2(acc[i][j][0], acc[i][j][1]);
                    *(uint32_t*)(g_Kh + o + 8*72) = packh2(acc[i][j][2], acc[i][j][3]);
                } else {                   // V: single fp16, transposed
                    size_t o = ((size_t)bh*DD + d)*264 + t;
                    g_Vth[o]           = __float2half_rn(acc[i][j][0]);
                    g_Vth[o + 264]     = __float2half_rn(acc[i][j][1]);
                    g_Vth[o + 8]       = __float2half_rn(acc[i][j][2]);
                    g_Vth[o + 264 + 8] = __float2half_rn(acc[i][j][3]);
                }
            } else {
                float2 bb = *(const float2*)(bp + nn);
                *(float2*)(outp + (size_t)m0 * CC + nn) =
                    make_float2(acc[i][j][0] + bb.x, acc[i][j][1] + bb.y);
                *(float2*)(outp + (size_t)(m0 + 8) * CC + nn) =
                    make_float2(acc[i][j][2] + bb.x, acc[i][j][3] + bb.y);
            }
        }
    }
}

// ---------------------------------------------------------------------------
// HMMA flash attention: S = (Qh+Ql)*K (2 prod), O += P*V (1 prod, P fp16).
// Load-balanced 16-row tiles (j=w and j=15-w -> exactly 5 tile-chunks/warp).
// Epilogue writes att as single fp16 (tiled layout for gemm<1>).
// ---------------------------------------------------------------------------
__global__ __launch_bounds__(256, 1) void attn_flash() {
    extern __shared__ __align__(128) char sma[];
    const int bh = blockIdx.x;
    const int tid = threadIdx.x, lane = tid & 31, w = tid >> 5;
    const int lr = lane >> 2, lc = lane & 3;
    const uint32_t sb = (uint32_t)__cvta_generic_to_shared(sma);
    const uint32_t mb = sb + ASZ;

    if (tid == 0) {
        mbar_init(mb, 1);
        fence_async();
        mbar_expect(mb, ASZ);
        bulk_g2s(sb + AQH, g_Qh  + (size_t)bh*TT*72,  36864, mb);
        bulk_g2s(sb + AQL, g_Ql  + (size_t)bh*TT*72,  36864, mb);
        bulk_g2s(sb + AKH, g_Kh  + (size_t)bh*TT*72,  36864, mb);
        bulk_g2s(sb + AVH, g_Vth + (size_t)bh*DD*264, 33792, mb);
    }
    __syncthreads();
    mbar_wait(mb, 0);

    const int b = bh / HH, h = bh % HH;

    #pragma unroll
    for (int half = 0; half < 2; half++) {
        const int jt = half ? (15 - w) : w;
        const int rowbase = jt * 16;
        const int cnt = (jt >> 2) + 1;
        const int diagc = jt >> 2;

        uint32_t qh[4][4], ql[4][4];
        #pragma unroll
        for (int ks = 0; ks < 4; ks++) {
            uint32_t off = (uint32_t)(rowbase + lr)*144 + (ks*16 + lc*2)*2;
            qh[ks][0] = *(const uint32_t*)(sma + AQH + off);
            qh[ks][1] = *(const uint32_t*)(sma + AQH + off + 8*144);
            qh[ks][2] = *(const uint32_t*)(sma + AQH + off + 16);
            qh[ks][3] = *(const uint32_t*)(sma + AQH + off + 8*144 + 16);
            ql[ks][0] = *(const uint32_t*)(sma + AQL + off);
            ql[ks][1] = *(const uint32_t*)(sma + AQL + off + 8*144);
            ql[ks][2] = *(const uint32_t*)(sma + AQL + off + 16);
            ql[ks][3] = *(const uint32_t*)(sma + AQL + off + 8*144 + 16);
        }

        float O[8][4];
        #pragma unroll
        for (int j = 0; j < 8; j++)
            #pragma unroll
            for (int r = 0; r < 4; r++) O[j][r] = 0.f;
        float rowm[2] = {-1e30f, -1e30f};
        float rowl[2] = {0.f, 0.f};

        for (int c = 0; c < cnt; c++) {
            const int s0 = c * 64;
            float S[8][4];
            #pragma unroll
            for (int n = 0; n < 8; n++)
                #pragma unroll
                for (int r = 0; r < 4; r++) S[n][r] = 0.f;

            #pragma unroll
            for (int ks = 0; ks < 4; ks++) {
                #pragma unroll
                for (int n = 0; n < 8; n++) {
                    uint32_t off = (uint32_t)(s0 + n*8 + lr)*144 + (ks*16 + lc*2)*2;
                    uint32_t kb2[2];
                    kb2[0] = *(const uint32_t*)(sma + AKH + off);
                    kb2[1] = *(const uint32_t*)(sma + AKH + off + 16);
                    mma_f16(S[n], qh[ks], kb2);
                    mma_f16(S[n], ql[ks], kb2);
                }
            }

            const bool diag = (c == diagc);
            const int trow = rowbase + lr;
            #pragma unroll
            for (int n = 0; n < 8; n++) {
                int scol = s0 + n*8 + lc*2;
                S[n][0] *= 0.125f; S[n][1] *= 0.125f;
                S[n][2] *= 0.125f; S[n][3] *= 0.125f;
                if (diag) {
                    if (scol     > trow)     S[n][0] = -1e30f;
                    if (scol + 1 > trow)     S[n][1] = -1e30f;
                    if (scol     > trow + 8) S[n][2] = -1e30f;
                    if (scol + 1 > trow + 8) S[n][3] = -1e30f;
                }
            }

            #pragma unroll
            for (int rg = 0; rg < 2; rg++) {
                float cm = -1e30f;
                #pragma unroll
                for (int n = 0; n < 8; n++) {
                    cm = fmaxf(cm, S[n][rg*2]);
                    cm = fmaxf(cm, S[n][rg*2+1]);
                }
                cm = fmaxf(cm, __shfl_xor_sync(0xffffffffu, cm, 1));
                cm = fmaxf(cm, __shfl_xor_sync(0xffffffffu, cm, 2));
                float mold = rowm[rg];
                float mn = fmaxf(mold, cm);
                float alpha = __expf(mold - mn);
                rowm[rg] = mn;
                float ls = 0.f;
                #pragma unroll
                for (int n = 0; n < 8; n++) {
                    float p0 = __expf(S[n][rg*2]   - mn);
                    float p1 = __expf(S[n][rg*2+1] - mn);
                    S[n][rg*2] = p0; S[n][rg*2+1] = p1;
                    ls += p0 + p1;
                }
                rowl[rg] = rowl[rg]*alpha + ls;
                #pragma unroll
                for (int j = 0; j < 8; j++) {
                    O[j][rg*2]   *= alpha;
                    O[j][rg*2+1] *= alpha;
                }
            }

            #pragma unroll
            for (int ks2 = 0; ks2 < 4; ks2++) {
                uint32_t ph[4];
                ph[0] = packh2(S[2*ks2][0],   S[2*ks2][1]);
                ph[1] = packh2(S[2*ks2][2],   S[2*ks2][3]);
                ph[2] = packh2(S[2*ks2+1][0], S[2*ks2+1][1]);
                ph[3] = packh2(S[2*ks2+1][2], S[2*ks2+1][3]);
                #pragma unroll
                for (int j = 0; j < 8; j++) {
                    uint32_t off = (uint32_t)(j*8 + lr)*528 + (s0 + ks2*16 + lc*2)*2;
                    uint32_t vb2[2];
                    vb2[0] = *(const uint32_t*)(sma + AVH + off);
                    vb2[1] = *(const uint32_t*)(sma + AVH + off + 16);
                    mma_f16(O[j], ph, vb2);
                }
            }
        }

        float linv0, linv1;
        {
            float lf = rowl[0];
            lf += __shfl_xor_sync(0xffffffffu, lf, 1);
            lf += __shfl_xor_sync(0xffffffffu, lf, 2);
            linv0 = 1.f / lf;
            lf = rowl[1];
            lf += __shfl_xor_sync(0xffffffffu, lf, 1);
            lf += __shfl_xor_sync(0xffffffffu, lf, 2);
            linv1 = 1.f / lf;
        }
        const int gm0 = b*TT + rowbase + lr;
        #pragma unroll
        for (int j = 0; j < 8; j++) {
            int n = h*DD + j*8 + lc*2;
            size_t o0 = tiled_idx(gm0, n);
            *(uint32_t*)(g_Ath + o0) = packh2(O[j][0]*linv0, O[j][1]*linv0);
            size_t o1 = tiled_idx(gm0 + 8, n);
            *(uint32_t*)(g_Ath + o1) = packh2(O[j][2]*linv1, O[j][3]*linv1);
        }
    }
}

// ---------------------------------------------------------------------------
extern "C" void kernel_launch(void* const* d_in, const int* in_sizes, int n_in,
                              void* d_out, int out_size) {
    const float* x  = (const float*)d_in[0];
    const float* Wq = (const float*)d_in[1];
    const float* Wk = (const float*)d_in[2];
    const float* Wv = (const float*)d_in[3];
    const float* Wp = (const float*)d_in[4];
    const float* bp = (const float*)d_in[5];
    float* out = (float*)d_out;

    prep<<<(XW + WTW + WPW) / 256, 256>>>(x, Wq, Wk, Wv, Wp);

    const int gsmem0 = NSTAGE * 3 * TILE_B + 48;   // 92208
    const int gsmem1 = NSTAGE * 2 * TILE_B + 48;   // 61488
    cudaFuncSetAttribute(gemm_tc<0>, cudaFuncAttributeMaxDynamicSharedMemorySize, gsmem0);
    cudaFuncSetAttribute(gemm_tc<1>, cudaFuncAttributeMaxDynamicSharedMemorySize, gsmem1);

    gemm_tc<0><<<dim3(NQKV/128, BT/128), 256, gsmem0>>>(nullptr, nullptr);

    cudaFuncSetAttribute(attn_flash, cudaFuncAttributeMaxDynamicSharedMemorySize, ASZ + 16);
    attn_flash<<<BB*HH, 256, ASZ + 16>>>();

    gemm_tc<1><<<dim3(CC/128, BT/128), 256, gsmem1>>>(bp, out);
}

// round 14
// speedup vs baseline: 2.2359x; 1.4026x over previous
#include <cuda_runtime.h>
#include <cuda_fp16.h>
#include <cstdint>

#define BB 64
#define TT 256
#define CC 384
#define HH 6
#define DD 64
#define BT (BB*TT)         // 16384
#define NQKV (3*HH*DD)     // 1152
#define PITCH 40           // fp16 elems per smem/gmem tile row
#define TILE_E 5120        // elems per 128x32 tile
#define TILE_B 10240       // bytes per tile
#define NCH 12             // K chunks (384/32)
#define NSTAGE 3

// prep work partition (8 elems per thread)
#define XW (BT*CC/8)       // 786432
#define WTW (NQKV*CC/8)    // 55296
#define WPW (CC*CC/8)      // 18432

// attention smem layout (bytes). Q/K pitch 72 fp16 (144B), Vt pitch 264 fp16 (528B)
#define AQH 0
#define AKH 36864
#define AVH 73728
#define ASZ 107520

// ---------------- static scratch (tiled/pitched fp16 layouts) ----------------
__device__ __align__(128) __half g_Xh[(size_t)128*NCH*TILE_E];
__device__ __align__(128) __half g_Wth[(size_t)9*NCH*TILE_E];
__device__ __align__(128) __half g_Ath[(size_t)128*NCH*TILE_E];
__device__ __align__(128) __half g_Wph[(size_t)3*NCH*TILE_E];
__device__ __align__(128) __half g_Qh[(size_t)BB*HH*TT*72];
__device__ __align__(128) __half g_Kh[(size_t)BB*HH*TT*72];
__device__ __align__(128) __half g_Vth[(size_t)BB*HH*DD*264];

// ---------------- helpers ----------------
__device__ __forceinline__ void bulk_g2s(uint32_t dst, const void* src, uint32_t bytes,
                                         uint32_t mbar) {
    asm volatile("cp.async.bulk.shared::cluster.global.mbarrier::complete_tx::bytes "
                 "[%0], [%1], %2, [%3];"
                 :: "r"(dst), "l"(src), "r"(bytes), "r"(mbar) : "memory");
}
__device__ __forceinline__ void mbar_init(uint32_t mbar, uint32_t cnt) {
    asm volatile("mbarrier.init.shared.b64 [%0], %1;" :: "r"(mbar), "r"(cnt) : "memory");
}
__device__ __forceinline__ void mbar_expect(uint32_t mbar, uint32_t bytes) {
    asm volatile("mbarrier.arrive.expect_tx.shared.b64 _, [%0], %1;"
                 :: "r"(mbar), "r"(bytes) : "memory");
}
__device__ __forceinline__ void mbar_arrive(uint32_t mbar) {
    asm volatile("mbarrier.arrive.shared.b64 _, [%0];" :: "r"(mbar) : "memory");
}
__device__ __forceinline__ void mbar_wait(uint32_t mbar, uint32_t parity) {
    asm volatile("{\n\t.reg .pred P;\n\t"
                 "WL_%=:\n\t"
                 "mbarrier.try_wait.parity.acquire.cta.shared::cta.b64 P, [%0], %1, 0x989680;\n\t"
                 "@P bra WD_%=;\n\t"
                 "bra WL_%=;\n\t"
                 "WD_%=:\n\t}"
                 :: "r"(mbar), "r"(parity) : "memory");
}
__device__ __forceinline__ void fence_async() {
    asm volatile("fence.proxy.async.shared::cta;" ::: "memory");
}
__device__ __forceinline__ void mma_f16(float* c, const uint32_t* a, const uint32_t* b) {
    asm volatile("mma.sync.aligned.m16n8k16.row.col.f32.f16.f16.f32 "
                 "{%0,%1,%2,%3}, {%4,%5,%6,%7}, {%8,%9}, {%0,%1,%2,%3};"
                 : "+f"(c[0]), "+f"(c[1]), "+f"(c[2]), "+f"(c[3])
                 : "r"(a[0]), "r"(a[1]), "r"(a[2]), "r"(a[3]),
                   "r"(b[0]), "r"(b[1]));
}
__device__ __forceinline__ void ldm_x4(uint32_t* r, uint32_t addr) {
    asm volatile("ldmatrix.sync.aligned.m8n8.x4.shared.b16 {%0,%1,%2,%3}, [%4];"
                 : "=r"(r[0]), "=r"(r[1]), "=r"(r[2]), "=r"(r[3]) : "r"(addr));
}
__device__ __forceinline__ uint32_t packh2(float x, float y) {
    __half hx = __float2half_rn(x), hy = __float2half_rn(y);
    uint16_t ux = *(uint16_t*)&hx, uy = *(uint16_t*)&hy;
    return (uint32_t)ux | ((uint32_t)uy << 16);
}
__device__ __forceinline__ size_t tiled_idx(int m, int k) {
    return ((size_t)(m >> 7) * NCH + (k >> 5)) * TILE_E + (m & 127) * PITCH + (k & 31);
}

// ---------------- fused prep (all single fp16) ----------------
__global__ void prep(const float* __restrict__ x,
                     const float* __restrict__ Wq, const float* __restrict__ Wk,
                     const float* __restrict__ Wv, const float* __restrict__ Wp) {
    int g = blockIdx.x * blockDim.x + threadIdx.x;
    if (g < XW) {
        int i = g * 8;
        int m = i / CC, k = i % CC;
        float4 v0 = *(const float4*)(x + i);
        float4 v1 = *(const float4*)(x + i + 4);
        __half h[8];
        float vv[8] = {v0.x,v0.y,v0.z,v0.w,v1.x,v1.y,v1.z,v1.w};
        #pragma unroll
        for (int j = 0; j < 8; j++) h[j] = __float2half_rn(vv[j]);
        *(uint4*)(g_Xh + tiled_idx(m, k)) = *(uint4*)h;
    } else if (g < XW + WTW) {
        int idx8 = g - XW;
        int n = idx8 / (CC/8), c0 = (idx8 % (CC/8)) * 8;
        int proj = n / (HH * DD), r = n % (HH * DD);
        int h = r / DD, d = r % DD;
        const float* W = (proj == 0) ? Wq : (proj == 1) ? Wk : Wv;
        size_t o = tiled_idx(n, c0);
        #pragma unroll
        for (int cc = 0; cc < 8; cc++)
            g_Wth[o + cc] = __float2half_rn(W[((size_t)h * CC + c0 + cc) * DD + d]);
    } else if (g < XW + WTW + WPW) {
        int i = (g - XW - WTW) * 8;
        int n = i / CC, k = i % CC;
        float4 v0 = *(const float4*)(Wp + i);
        float4 v1 = *(const float4*)(Wp + i + 4);
        __half h[8];
        float vv[8] = {v0.x,v0.y,v0.z,v0.w,v1.x,v1.y,v1.z,v1.w};
        #pragma unroll
        for (int j = 0; j < 8; j++) h[j] = __float2half_rn(vv[j]);
        *(uint4*)(g_Wph + tiled_idx(n, k)) = *(uint4*)h;
    }
}

// ---------------------------------------------------------------------------
// HMMA GEMM, 1-product fp16, 3-stage bulk pipeline (2 tiles/stage).
// MODE 0: A=X, B=Wt; emit Q,K (pitch 72) and Vt (pitch 264), single fp16.
// MODE 1: A=att, B=Wp; +bias -> fp32 out.
// ---------------------------------------------------------------------------
template<int MODE>
__global__ __launch_bounds__(256, 2) void gemm_tc(const float* __restrict__ bp,
                                                  float* __restrict__ outp) {
    extern __shared__ __align__(128) char sm[];
    const __half* As = (MODE == 0) ? g_Xh  : g_Ath;
    const __half* Bs = (MODE == 0) ? g_Wth : g_Wph;

    const int tid = threadIdx.x, lane = tid & 31, wid = tid >> 5;
    const int wm = wid & 3, wn = wid >> 2;
    const int lr = lane >> 2, lc = lane & 3;
    const int rb = blockIdx.y, cb = blockIdx.x;
    const int row0 = rb * 128, col0 = cb * 128;
    const uint32_t sbase = (uint32_t)__cvta_generic_to_shared(sm);
    const uint32_t barb = sbase + NSTAGE * 2 * TILE_B;

    uint32_t aoff[2];
    #pragma unroll
    for (int mt = 0; mt < 2; mt++)
        aoff[mt] = (uint32_t)(wm*32 + mt*16 + (lane & 15)) * PITCH + ((lane >> 4) & 1) * 8;
    uint32_t boff[4];
    #pragma unroll
    for (int jj = 0; jj < 4; jj++)
        boff[jj] = (uint32_t)(wn*64 + jj*16 + ((lane >> 4) & 1)*8 + (lane & 7)) * PITCH
                   + ((lane >> 3) & 1) * 8;

    if (tid == 0) {
        #pragma unroll
        for (int s = 0; s < NSTAGE; s++) {
            mbar_init(barb + s*8, 1);
            mbar_init(barb + (NSTAGE + s)*8, 8);
        }
    }
    __syncthreads();

    auto issue = [&](int s, int c) {
        uint32_t st = sbase + s * 2 * TILE_B;
        uint32_t mb = barb + s*8;
        fence_async();
        mbar_expect(mb, 2 * TILE_B);
        bulk_g2s(st,          As + ((size_t)rb*NCH + c)*TILE_E, TILE_B, mb);
        bulk_g2s(st + TILE_B, Bs + ((size_t)cb*NCH + c)*TILE_E, TILE_B, mb);
    };

    float acc[2][8][4];
    #pragma unroll
    for (int i = 0; i < 2; i++)
        #pragma unroll
        for (int j = 0; j < 8; j++)
            #pragma unroll
            for (int r = 0; r < 4; r++) acc[i][j][r] = 0.f;

    if (tid == 0) { issue(0, 0); issue(1, 1); issue(2, 2); }

    for (int kc = 0; kc < NCH; kc++) {
        int buf = kc % NSTAGE;
        int par = (kc / NSTAGE) & 1;
        mbar_wait(barb + buf*8, par);

        const uint32_t sbuf = sbase + buf * 2 * TILE_B;
        #pragma unroll
        for (int ks = 0; ks < 2; ks++) {
            const uint32_t kb = ks * 16;
            uint32_t ah[2][4];
            #pragma unroll
            for (int mt = 0; mt < 2; mt++)
                ldm_x4(ah[mt], sbuf + (aoff[mt] + kb) * 2);
            #pragma unroll
            for (int jj = 0; jj < 4; jj++) {
                uint32_t bh4[4];
                ldm_x4(bh4, sbuf + TILE_B + (boff[jj] + kb) * 2);
                #pragma unroll
                for (int mt = 0; mt < 2; mt++) {
                    mma_f16(acc[mt][2*jj],   ah[mt], bh4);
                    mma_f16(acc[mt][2*jj+1], ah[mt], bh4 + 2);
                }
            }
        }
        if (lane == 0) mbar_arrive(barb + (NSTAGE + buf)*8);
        if (tid == 0 && kc + NSTAGE < NCH) {
            mbar_wait(barb + (NSTAGE + buf)*8, par);
            issue(buf, kc + NSTAGE);
        }
    }

    // epilogue
    #pragma unroll
    for (int i = 0; i < 2; i++) {
        int m0 = row0 + wm*32 + i*16 + lr;
        #pragma unroll
        for (int j = 0; j < 8; j++) {
            int nn = col0 + wn*64 + j*8 + lc*2;
            if (MODE == 0) {
                int proj = nn / (HH*DD);
                int rem  = nn % (HH*DD);
                int h = rem / DD, d = rem % DD;
                int b = m0 / TT, t = m0 % TT;
                int bh = b*HH + h;
                if (proj < 2) {            // Q or K: single fp16, pitch 72
                    __half* dst = (proj == 0) ? g_Qh : g_Kh;
                    size_t o = ((size_t)bh*TT + t)*72 + d;
                    *(uint32_t*)(dst + o)        = packh2(acc[i][j][0], acc[i][j][1]);
                    *(uint32_t*)(dst + o + 8*72) = packh2(acc[i][j][2], acc[i][j][3]);
                } else {                   // V: single fp16, transposed, pitch 264
                    size_t o = ((size_t)bh*DD + d)*264 + t;
                    g_Vth[o]           = __float2half_rn(acc[i][j][0]);
                    g_Vth[o + 264]     = __float2half_rn(acc[i][j][1]);
                    g_Vth[o + 8]       = __float2half_rn(acc[i][j][2]);
                    g_Vth[o + 264 + 8] = __float2half_rn(acc[i][j][3]);
                }
            } else {
                float2 bb = *(const float2*)(bp + nn);
                *(float2*)(outp + (size_t)m0 * CC + nn) =
                    make_float2(acc[i][j][0] + bb.x, acc[i][j][1] + bb.y);
                *(float2*)(outp + (size_t)(m0 + 8) * CC + nn) =
                    make_float2(acc[i][j][2] + bb.x, acc[i][j][3] + bb.y);
            }
        }
    }
}

// ---------------------------------------------------------------------------
// HMMA flash attention, fully 1-product fp16: S = Q*K, O += P*V.
// 2 CTAs/SM (105KB smem). Load-balanced tiles j=w / j=15-w (5 chunks/warp).
// ---------------------------------------------------------------------------
__global__ __launch_bounds__(256, 2) void attn_flash() {
    extern __shared__ __align__(128) char sma[];
    const int bh = blockIdx.x;
    const int tid = threadIdx.x, lane = tid & 31, w = tid >> 5;
    const int lr = lane >> 2, lc = lane & 3;
    const uint32_t sb = (uint32_t)__cvta_generic_to_shared(sma);
    const uint32_t mb = sb + ASZ;

    if (tid == 0) {
        mbar_init(mb, 1);
        fence_async();
        mbar_expect(mb, ASZ);
        bulk_g2s(sb + AQH, g_Qh  + (size_t)bh*TT*72,  36864, mb);
        bulk_g2s(sb + AKH, g_Kh  + (size_t)bh*TT*72,  36864, mb);
        bulk_g2s(sb + AVH, g_Vth + (size_t)bh*DD*264, 33792, mb);
    }
    __syncthreads();
    mbar_wait(mb, 0);

    const int b = bh / HH, h = bh % HH;

    #pragma unroll
    for (int half = 0; half < 2; half++) {
        const int jt = half ? (15 - w) : w;
        const int rowbase = jt * 16;
        const int cnt = (jt >> 2) + 1;
        const int diagc = jt >> 2;

        uint32_t qh[4][4];
        #pragma unroll
        for (int ks = 0; ks < 4; ks++) {
            uint32_t off = (uint32_t)(rowbase + lr)*144 + (ks*16 + lc*2)*2;
            qh[ks][0] = *(const uint32_t*)(sma + AQH + off);
            qh[ks][1] = *(const uint32_t*)(sma + AQH + off + 8*144);
            qh[ks][2] = *(const uint32_t*)(sma + AQH + off + 16);
            qh[ks][3] = *(const uint32_t*)(sma + AQH + off + 8*144 + 16);
        }

        float O[8][4];
        #pragma unroll
        for (int j = 0; j < 8; j++)
            #pragma unroll
            for (int r = 0; r < 4; r++) O[j][r] = 0.f;
        float rowm[2] = {-1e30f, -1e30f};
        float rowl[2] = {0.f, 0.f};

        for (int c = 0; c < cnt; c++) {
            const int s0 = c * 64;
            float S[8][4];
            #pragma unroll
            for (int n = 0; n < 8; n++)
                #pragma unroll
                for (int r = 0; r < 4; r++) S[n][r] = 0.f;

            #pragma unroll
            for (int ks = 0; ks < 4; ks++) {
                #pragma unroll
                for (int n = 0; n < 8; n++) {
                    uint32_t off = (uint32_t)(s0 + n*8 + lr)*144 + (ks*16 + lc*2)*2;
                    uint32_t kb2[2];
                    kb2[0] = *(const uint32_t*)(sma + AKH + off);
                    kb2[1] = *(const uint32_t*)(sma + AKH + off + 16);
                    mma_f16(S[n], qh[ks], kb2);
                }
            }

            const bool diag = (c == diagc);
            const int trow = rowbase + lr;
            #pragma unroll
            for (int n = 0; n < 8; n++) {
                int scol = s0 + n*8 + lc*2;
                S[n][0] *= 0.125f; S[n][1] *= 0.125f;
                S[n][2] *= 0.125f; S[n][3] *= 0.125f;
                if (diag) {
                    if (scol     > trow)     S[n][0] = -1e30f;
                    if (scol + 1 > trow)     S[n][1] = -1e30f;
                    if (scol     > trow + 8) S[n][2] = -1e30f;
                    if (scol + 1 > trow + 8) S[n][3] = -1e30f;
                }
            }

            #pragma unroll
            for (int rg = 0; rg < 2; rg++) {
                float cm = -1e30f;
                #pragma unroll
                for (int n = 0; n < 8; n++) {
                    cm = fmaxf(cm, S[n][rg*2]);
                    cm = fmaxf(cm, S[n][rg*2+1]);
                }
                cm = fmaxf(cm, __shfl_xor_sync(0xffffffffu, cm, 1));
                cm = fmaxf(cm, __shfl_xor_sync(0xffffffffu, cm, 2));
                float mold = rowm[rg];
                float mn = fmaxf(mold, cm);
                float alpha = __expf(mold - mn);
                rowm[rg] = mn;
                float ls = 0.f;
                #pragma unroll
                for (int n = 0; n < 8; n++) {
                    float p0 = __expf(S[n][rg*2]   - mn);
                    float p1 = __expf(S[n][rg*2+1] - mn);
                    S[n][rg*2] = p0; S[n][rg*2+1] = p1;
                    ls += p0 + p1;
                }
                rowl[rg] = rowl[rg]*alpha + ls;
                #pragma unroll
                for (int j = 0; j < 8; j++) {
                    O[j][rg*2]   *= alpha;
                    O[j][rg*2+1] *= alpha;
                }
            }

            #pragma unroll
            for (int ks2 = 0; ks2 < 4; ks2++) {
                uint32_t ph[4];
                ph[0] = packh2(S[2*ks2][0],   S[2*ks2][1]);
                ph[1] = packh2(S[2*ks2][2],   S[2*ks2][3]);
                ph[2] = packh2(S[2*ks2+1][0], S[2*ks2+1][1]);
                ph[3] = packh2(S[2*ks2+1][2], S[2*ks2+1][3]);
                #pragma unroll
                for (int j = 0; j < 8; j++) {
                    uint32_t off = (uint32_t)(j*8 + lr)*528 + (s0 + ks2*16 + lc*2)*2;
                    uint32_t vb2[2];
                    vb2[0] = *(const uint32_t*)(sma + AVH + off);
                    vb2[1] = *(const uint32_t*)(sma + AVH + off + 16);
                    mma_f16(O[j], ph, vb2);
                }
            }
        }

        float linv0, linv1;
        {
            float lf = rowl[0];
            lf += __shfl_xor_sync(0xffffffffu, lf, 1);
            lf += __shfl_xor_sync(0xffffffffu, lf, 2);
            linv0 = 1.f / lf;
            lf = rowl[1];
            lf += __shfl_xor_sync(0xffffffffu, lf, 1);
            lf += __shfl_xor_sync(0xffffffffu, lf, 2);
            linv1 = 1.f / lf;
        }
        const int gm0 = b*TT + rowbase + lr;
        #pragma unroll
        for (int j = 0; j < 8; j++) {
            int n = h*DD + j*8 + lc*2;
            size_t o0 = tiled_idx(gm0, n);
            *(uint32_t*)(g_Ath + o0) = packh2(O[j][0]*linv0, O[j][1]*linv0);
            size_t o1 = tiled_idx(gm0 + 8, n);
            *(uint32_t*)(g_Ath + o1) = packh2(O[j][2]*linv1, O[j][3]*linv1);
        }
    }
}

// ---------------------------------------------------------------------------
extern "C" void kernel_launch(void* const* d_in, const int* in_sizes, int n_in,
                              void* d_out, int out_size) {
    const float* x  = (const float*)d_in[0];
    const float* Wq = (const float*)d_in[1];
    const float* Wk = (const float*)d_in[2];
    const float* Wv = (const float*)d_in[3];
    const float* Wp = (const float*)d_in[4];
    const float* bp = (const float*)d_in[5];
    float* out = (float*)d_out;

    prep<<<(XW + WTW + WPW) / 256, 256>>>(x, Wq, Wk, Wv, Wp);

    const int gsmem = NSTAGE * 2 * TILE_B + 48;   // 61488
    cudaFuncSetAttribute(gemm_tc<0>, cudaFuncAttributeMaxDynamicSharedMemorySize, gsmem);
    cudaFuncSetAttribute(gemm_tc<1>, cudaFuncAttributeMaxDynamicSharedMemorySize, gsmem);

    gemm_tc<0><<<dim3(NQKV/128, BT/128), 256, gsmem>>>(nullptr, nullptr);

    cudaFuncSetAttribute(attn_flash, cudaFuncAttributeMaxDynamicSharedMemorySize, ASZ + 16);
    attn_flash<<<BB*HH, 256, ASZ + 16>>>();

    gemm_tc<1><<<dim3(CC/128, BT/128), 256, gsmem>>>(bp, out);
}

// round 15
// speedup vs baseline: 2.4161x; 1.0806x over previous
#include <cuda_runtime.h>
#include <cuda_fp16.h>
#include <cstdint>

#define BB 64
#define TT 256
#define CC 384
#define HH 6
#define DD 64
#define BT (BB*TT)         // 16384
#define NQKV (3*HH*DD)     // 1152
#define CPITCH 72          // fp16 elems per tile row (144B, 9-phase conflict-free)
#define TILE_E 9216        // elems per 128x64 tile (pitch 72)
#define TILE_B 18432       // bytes per tile
#define NCH 6              // K chunks (384/64)
#define NSTAGE 3

// prep work partition (8 elems per thread)
#define XW (BT*CC/8)       // 786432
#define WTW (NQKV*CC/8)    // 55296
#define WPW (CC*CC/8)      // 18432

// attention smem layout (bytes). K pitch 72 fp16 (144B), Vt pitch 264 fp16 (528B)
#define AKH 0
#define AVH 36864
#define ASZ 70656

// ---------------- static scratch (tiled/pitched fp16 layouts) ----------------
__device__ __align__(128) __half g_Xh[(size_t)128*NCH*TILE_E];
__device__ __align__(128) __half g_Wth[(size_t)9*NCH*TILE_E];
__device__ __align__(128) __half g_Ath[(size_t)128*NCH*TILE_E];
__device__ __align__(128) __half g_Wph[(size_t)3*NCH*TILE_E];
__device__ __align__(128) __half g_Qh[(size_t)BB*HH*TT*72];
__device__ __align__(128) __half g_Kh[(size_t)BB*HH*TT*72];
__device__ __align__(128) __half g_Vth[(size_t)BB*HH*DD*264];

// ---------------- helpers ----------------
__device__ __forceinline__ void bulk_g2s(uint32_t dst, const void* src, uint32_t bytes,
                                         uint32_t mbar) {
    asm volatile("cp.async.bulk.shared::cluster.global.mbarrier::complete_tx::bytes "
                 "[%0], [%1], %2, [%3];"
                 :: "r"(dst), "l"(src), "r"(bytes), "r"(mbar) : "memory");
}
__device__ __forceinline__ void mbar_init(uint32_t mbar, uint32_t cnt) {
    asm volatile("mbarrier.init.shared.b64 [%0], %1;" :: "r"(mbar), "r"(cnt) : "memory");
}
__device__ __forceinline__ void mbar_expect(uint32_t mbar, uint32_t bytes) {
    asm volatile("mbarrier.arrive.expect_tx.shared.b64 _, [%0], %1;"
                 :: "r"(mbar), "r"(bytes) : "memory");
}
__device__ __forceinline__ void mbar_arrive(uint32_t mbar) {
    asm volatile("mbarrier.arrive.shared.b64 _, [%0];" :: "r"(mbar) : "memory");
}
__device__ __forceinline__ void mbar_wait(uint32_t mbar, uint32_t parity) {
    asm volatile("{\n\t.reg .pred P;\n\t"
                 "WL_%=:\n\t"
                 "mbarrier.try_wait.parity.acquire.cta.shared::cta.b64 P, [%0], %1, 0x989680;\n\t"
                 "@P bra WD_%=;\n\t"
                 "bra WL_%=;\n\t"
                 "WD_%=:\n\t}"
                 :: "r"(mbar), "r"(parity) : "memory");
}
__device__ __forceinline__ void fence_async() {
    asm volatile("fence.proxy.async.shared::cta;" ::: "memory");
}
__device__ __forceinline__ void mma_f16(float* c, const uint32_t* a, const uint32_t* b) {
    asm volatile("mma.sync.aligned.m16n8k16.row.col.f32.f16.f16.f32 "
                 "{%0,%1,%2,%3}, {%4,%5,%6,%7}, {%8,%9}, {%0,%1,%2,%3};"
                 : "+f"(c[0]), "+f"(c[1]), "+f"(c[2]), "+f"(c[3])
                 : "r"(a[0]), "r"(a[1]), "r"(a[2]), "r"(a[3]),
                   "r"(b[0]), "r"(b[1]));
}
__device__ __forceinline__ void ldm_x4(uint32_t* r, uint32_t addr) {
    asm volatile("ldmatrix.sync.aligned.m8n8.x4.shared.b16 {%0,%1,%2,%3}, [%4];"
                 : "=r"(r[0]), "=r"(r[1]), "=r"(r[2]), "=r"(r[3]) : "r"(addr));
}
__device__ __forceinline__ uint32_t packh2(float x, float y) {
    __half hx = __float2half_rn(x), hy = __float2half_rn(y);
    uint16_t ux = *(uint16_t*)&hx, uy = *(uint16_t*)&hy;
    return (uint32_t)ux | ((uint32_t)uy << 16);
}
__device__ __forceinline__ size_t tiled_idx(int m, int k) {   // 128-row blocks, 64-col chunks
    return ((size_t)(m >> 7) * NCH + (k >> 6)) * TILE_E + (m & 127) * CPITCH + (k & 63);
}

// ---------------- fused prep (all single fp16, tiled) ----------------
__global__ void prep(const float* __restrict__ x,
                     const float* __restrict__ Wq, const float* __restrict__ Wk,
                     const float* __restrict__ Wv, const float* __restrict__ Wp) {
    int g = blockIdx.x * blockDim.x + threadIdx.x;
    if (g < XW) {
        int i = g * 8;
        int m = i / CC, k = i % CC;
        float4 v0 = *(const float4*)(x + i);
        float4 v1 = *(const float4*)(x + i + 4);
        __half h[8];
        float vv[8] = {v0.x,v0.y,v0.z,v0.w,v1.x,v1.y,v1.z,v1.w};
        #pragma unroll
        for (int j = 0; j < 8; j++) h[j] = __float2half_rn(vv[j]);
        *(uint4*)(g_Xh + tiled_idx(m, k)) = *(uint4*)h;
    } else if (g < XW + WTW) {
        int idx8 = g - XW;
        int n = idx8 / (CC/8), c0 = (idx8 % (CC/8)) * 8;
        int proj = n / (HH * DD), r = n % (HH * DD);
        int h = r / DD, d = r % DD;
        const float* W = (proj == 0) ? Wq : (proj == 1) ? Wk : Wv;
        size_t o = tiled_idx(n, c0);
        #pragma unroll
        for (int cc = 0; cc < 8; cc++)
            g_Wth[o + cc] = __float2half_rn(W[((size_t)h * CC + c0 + cc) * DD + d]);
    } else if (g < XW + WTW + WPW) {
        int i = (g - XW - WTW) * 8;
        int n = i / CC, k = i % CC;
        float4 v0 = *(const float4*)(Wp + i);
        float4 v1 = *(const float4*)(Wp + i + 4);
        __half h[8];
        float vv[8] = {v0.x,v0.y,v0.z,v0.w,v1.x,v1.y,v1.z,v1.w};
        #pragma unroll
        for (int j = 0; j < 8; j++) h[j] = __float2half_rn(vv[j]);
        *(uint4*)(g_Wph + tiled_idx(n, k)) = *(uint4*)h;
    }
}

// ---------------------------------------------------------------------------
// HMMA GEMM, 1-product fp16, BK=64 chunks, 3-stage bulk pipeline.
// MODE 0: A=X, B=Wt; emit Q,K (pitch 72) and Vt (pitch 264), single fp16.
// MODE 1: A=att, B=Wp; +bias -> fp32 out.
// ---------------------------------------------------------------------------
template<int MODE>
__global__ __launch_bounds__(256, 2) void gemm_tc(const float* __restrict__ bp,
                                                  float* __restrict__ outp) {
    extern __shared__ __align__(128) char sm[];
    const __half* As = (MODE == 0) ? g_Xh  : g_Ath;
    const __half* Bs = (MODE == 0) ? g_Wth : g_Wph;

    const int tid = threadIdx.x, lane = tid & 31, wid = tid >> 5;
    const int wm = wid & 3, wn = wid >> 2;
    const int lr = lane >> 2, lc = lane & 3;
    const int rb = blockIdx.y, cb = blockIdx.x;
    const int row0 = rb * 128, col0 = cb * 128;
    const uint32_t sbase = (uint32_t)__cvta_generic_to_shared(sm);
    const uint32_t barb = sbase + NSTAGE * 2 * TILE_B;

    uint32_t aoff[2];
    #pragma unroll
    for (int mt = 0; mt < 2; mt++)
        aoff[mt] = (uint32_t)(wm*32 + mt*16 + (lane & 15)) * CPITCH + ((lane >> 4) & 1) * 8;
    uint32_t boff[4];
    #pragma unroll
    for (int jj = 0; jj < 4; jj++)
        boff[jj] = (uint32_t)(wn*64 + jj*16 + ((lane >> 4) & 1)*8 + (lane & 7)) * CPITCH
                   + ((lane >> 3) & 1) * 8;

    if (tid == 0) {
        #pragma unroll
        for (int s = 0; s < NSTAGE; s++) {
            mbar_init(barb + s*8, 1);
            mbar_init(barb + (NSTAGE + s)*8, 8);
        }
    }
    __syncthreads();

    auto issue = [&](int s, int c) {
        uint32_t st = sbase + s * 2 * TILE_B;
        uint32_t mb = barb + s*8;
        fence_async();
        mbar_expect(mb, 2 * TILE_B);
        bulk_g2s(st,          As + ((size_t)rb*NCH + c)*TILE_E, TILE_B, mb);
        bulk_g2s(st + TILE_B, Bs + ((size_t)cb*NCH + c)*TILE_E, TILE_B, mb);
    };

    float acc[2][8][4];
    #pragma unroll
    for (int i = 0; i < 2; i++)
        #pragma unroll
        for (int j = 0; j < 8; j++)
            #pragma unroll
            for (int r = 0; r < 4; r++) acc[i][j][r] = 0.f;

    if (tid == 0) { issue(0, 0); issue(1, 1); issue(2, 2); }

    for (int kc = 0; kc < NCH; kc++) {
        int buf = kc % NSTAGE;
        int par = (kc / NSTAGE) & 1;
        mbar_wait(barb + buf*8, par);

        const uint32_t sbuf = sbase + buf * 2 * TILE_B;
        #pragma unroll
        for (int ks = 0; ks < 4; ks++) {
            const uint32_t kb = ks * 16;
            uint32_t ah[2][4];
            #pragma unroll
            for (int mt = 0; mt < 2; mt++)
                ldm_x4(ah[mt], sbuf + (aoff[mt] + kb) * 2);
            #pragma unroll
            for (int jj = 0; jj < 4; jj++) {
                uint32_t bh4[4];
                ldm_x4(bh4, sbuf + TILE_B + (boff[jj] + kb) * 2);
                #pragma unroll
                for (int mt = 0; mt < 2; mt++) {
                    mma_f16(acc[mt][2*jj],   ah[mt], bh4);
                    mma_f16(acc[mt][2*jj+1], ah[mt], bh4 + 2);
                }
            }
        }
        if (lane == 0) mbar_arrive(barb + (NSTAGE + buf)*8);
        if (tid == 0 && kc + NSTAGE < NCH) {
            mbar_wait(barb + (NSTAGE + buf)*8, par);
            issue(buf, kc + NSTAGE);
        }
    }

    // epilogue
    #pragma unroll
    for (int i = 0; i < 2; i++) {
        int m0 = row0 + wm*32 + i*16 + lr;
        #pragma unroll
        for (int j = 0; j < 8; j++) {
            int nn = col0 + wn*64 + j*8 + lc*2;
            if (MODE == 0) {
                int proj = nn / (HH*DD);
                int rem  = nn % (HH*DD);
                int h = rem / DD, d = rem % DD;
                int b = m0 / TT, t = m0 % TT;
                int bh = b*HH + h;
                if (proj < 2) {            // Q or K: single fp16, pitch 72
                    __half* dst = (proj == 0) ? g_Qh : g_Kh;
                    size_t o = ((size_t)bh*TT + t)*72 + d;
                    *(uint32_t*)(dst + o)        = packh2(acc[i][j][0], acc[i][j][1]);
                    *(uint32_t*)(dst + o + 8*72) = packh2(acc[i][j][2], acc[i][j][3]);
                } else {                   // V: single fp16, transposed, pitch 264
                    size_t o = ((size_t)bh*DD + d)*264 + t;
                    g_Vth[o]           = __float2half_rn(acc[i][j][0]);
                    g_Vth[o + 264]     = __float2half_rn(acc[i][j][1]);
                    g_Vth[o + 8]       = __float2half_rn(acc[i][j][2]);
                    g_Vth[o + 264 + 8] = __float2half_rn(acc[i][j][3]);
                }
            } else {
                float2 bb = *(const float2*)(bp + nn);
                *(float2*)(outp + (size_t)m0 * CC + nn) =
                    make_float2(acc[i][j][0] + bb.x, acc[i][j][1] + bb.y);
                *(float2*)(outp + (size_t)(m0 + 8) * CC + nn) =
                    make_float2(acc[i][j][2] + bb.x, acc[i][j][3] + bb.y);
            }
        }
    }
}

// ---------------------------------------------------------------------------
// HMMA flash attention, 1-product fp16. K+Vt bulk-staged in smem (70.7KB);
// Q fragments loaded directly from gmem (hoisted once per tile).
// 2 CTAs/SM. Load-balanced tiles j=w / j=15-w (5 chunks/warp).
// ---------------------------------------------------------------------------
__global__ __launch_bounds__(256, 2) void attn_flash() {
    extern __shared__ __align__(128) char sma[];
    const int bh = blockIdx.x;
    const int tid = threadIdx.x, lane = tid & 31, w = tid >> 5;
    const int lr = lane >> 2, lc = lane & 3;
    const uint32_t sb = (uint32_t)__cvta_generic_to_shared(sma);
    const uint32_t mb = sb + ASZ;

    if (tid == 0) {
        mbar_init(mb, 1);
        fence_async();
        mbar_expect(mb, ASZ);
        bulk_g2s(sb + AKH, g_Kh  + (size_t)bh*TT*72,  36864, mb);
        bulk_g2s(sb + AVH, g_Vth + (size_t)bh*DD*264, 33792, mb);
    }
    __syncthreads();
    mbar_wait(mb, 0);

    const int b = bh / HH, h = bh % HH;
    const __half* qg = g_Qh + (size_t)bh*TT*72;

    #pragma unroll
    for (int half = 0; half < 2; half++) {
        const int jt = half ? (15 - w) : w;
        const int rowbase = jt * 16;
        const int cnt = (jt >> 2) + 1;
        const int diagc = jt >> 2;

        // Q fragments direct from gmem (once per tile)
        uint32_t qh[4][4];
        #pragma unroll
        for (int ks = 0; ks < 4; ks++) {
            size_t off = (size_t)(rowbase + lr)*72 + ks*16 + lc*2;
            qh[ks][0] = *(const uint32_t*)(qg + off);
            qh[ks][1] = *(const uint32_t*)(qg + off + 8*72);
            qh[ks][2] = *(const uint32_t*)(qg + off + 8);
            qh[ks][3] = *(const uint32_t*)(qg + off + 8*72 + 8);
        }

        float O[8][4];
        #pragma unroll
        for (int j = 0; j < 8; j++)
            #pragma unroll
            for (int r = 0; r < 4; r++) O[j][r] = 0.f;
        float rowm[2] = {-1e30f, -1e30f};
        float rowl[2] = {0.f, 0.f};

        for (int c = 0; c < cnt; c++) {
            const int s0 = c * 64;
            float S[8][4];
            #pragma unroll
            for (int n = 0; n < 8; n++)
                #pragma unroll
                for (int r = 0; r < 4; r++) S[n][r] = 0.f;

            #pragma unroll
            for (int ks = 0; ks < 4; ks++) {
                #pragma unroll
                for (int n = 0; n < 8; n++) {
                    uint32_t off = (uint32_t)(s0 + n*8 + lr)*144 + (ks*16 + lc*2)*2;
                    uint32_t kb2[2];
                    kb2[0] = *(const uint32_t*)(sma + AKH + off);
                    kb2[1] = *(const uint32_t*)(sma + AKH + off + 16);
                    mma_f16(S[n], qh[ks], kb2);
                }
            }

            const bool diag = (c == diagc);
            const int trow = rowbase + lr;
            #pragma unroll
            for (int n = 0; n < 8; n++) {
                int scol = s0 + n*8 + lc*2;
                S[n][0] *= 0.125f; S[n][1] *= 0.125f;
                S[n][2] *= 0.125f; S[n][3] *= 0.125f;
                if (diag) {
                    if (scol     > trow)     S[n][0] = -1e30f;
                    if (scol + 1 > trow)     S[n][1] = -1e30f;
                    if (scol     > trow + 8) S[n][2] = -1e30f;
                    if (scol + 1 > trow + 8) S[n][3] = -1e30f;
                }
            }

            #pragma unroll
            for (int rg = 0; rg < 2; rg++) {
                float cm = -1e30f;
                #pragma unroll
                for (int n = 0; n < 8; n++) {
                    cm = fmaxf(cm, S[n][rg*2]);
                    cm = fmaxf(cm, S[n][rg*2+1]);
                }
                cm = fmaxf(cm, __shfl_xor_sync(0xffffffffu, cm, 1));
                cm = fmaxf(cm, __shfl_xor_sync(0xffffffffu, cm, 2));
                float mold = rowm[rg];
                float mn = fmaxf(mold, cm);
                float alpha = __expf(mold - mn);
                rowm[rg] = mn;
                float ls = 0.f;
                #pragma unroll
                for (int n = 0; n < 8; n++) {
                    float p0 = __expf(S[n][rg*2]   - mn);
                    float p1 = __expf(S[n][rg*2+1] - mn);
                    S[n][rg*2] = p0; S[n][rg*2+1] = p1;
                    ls += p0 + p1;
                }
                rowl[rg] = rowl[rg]*alpha + ls;
                #pragma unroll
                for (int j = 0; j < 8; j++) {
                    O[j][rg*2]   *= alpha;
                    O[j][rg*2+1] *= alpha;
                }
            }

            #pragma unroll
            for (int ks2 = 0; ks2 < 4; ks2++) {
                uint32_t ph[4];
                ph[0] = packh2(S[2*ks2][0],   S[2*ks2][1]);
                ph[1] = packh2(S[2*ks2][2],   S[2*ks2][3]);
                ph[2] = packh2(S[2*ks2+1][0], S[2*ks2+1][1]);
                ph[3] = packh2(S[2*ks2+1][2], S[2*ks2+1][3]);
                #pragma unroll
                for (int j = 0; j < 8; j++) {
                    uint32_t off = (uint32_t)(j*8 + lr)*528 + (s0 + ks2*16 + lc*2)*2;
                    uint32_t vb2[2];
                    vb2[0] = *(const uint32_t*)(sma + AVH + off);
                    vb2[1] = *(const uint32_t*)(sma + AVH + off + 16);
                    mma_f16(O[j], ph, vb2);
                }
            }
        }

        float linv0, linv1;
        {
            float lf = rowl[0];
            lf += __shfl_xor_sync(0xffffffffu, lf, 1);
            lf += __shfl_xor_sync(0xffffffffu, lf, 2);
            linv0 = 1.f / lf;
            lf = rowl[1];
            lf += __shfl_xor_sync(0xffffffffu, lf, 1);
            lf += __shfl_xor_sync(0xffffffffu, lf, 2);
            linv1 = 1.f / lf;
        }
        const int gm0 = b*TT + rowbase + lr;
        #pragma unroll
        for (int j = 0; j < 8; j++) {
            int n = h*DD + j*8 + lc*2;
            size_t o0 = tiled_idx(gm0, n);
            *(uint32_t*)(g_Ath + o0) = packh2(O[j][0]*linv0, O[j][1]*linv0);
            size_t o1 = tiled_idx(gm0 + 8, n);
            *(uint32_t*)(g_Ath + o1) = packh2(O[j][2]*linv1, O[j][3]*linv1);
        }
    }
}

// ---------------------------------------------------------------------------
extern "C" void kernel_launch(void* const* d_in, const int* in_sizes, int n_in,
                              void* d_out, int out_size) {
    const float* x  = (const float*)d_in[0];
    const float* Wq = (const float*)d_in[1];
    const float* Wk = (const float*)d_in[2];
    const float* Wv = (const float*)d_in[3];
    const float* Wp = (const float*)d_in[4];
    const float* bp = (const float*)d_in[5];
    float* out = (float*)d_out;

    prep<<<(XW + WTW + WPW) / 256, 256>>>(x, Wq, Wk, Wv, Wp);

    const int gsmem = NSTAGE * 2 * TILE_B + 48;   // 110640
    cudaFuncSetAttribute(gemm_tc<0>, cudaFuncAttributeMaxDynamicSharedMemorySize, gsmem);
    cudaFuncSetAttribute(gemm_tc<1>, cudaFuncAttributeMaxDynamicSharedMemorySize, gsmem);

    gemm_tc<0><<<dim3(NQKV/128, BT/128), 256, gsmem>>>(nullptr, nullptr);

    cudaFuncSetAttribute(attn_flash, cudaFuncAttributeMaxDynamicSharedMemorySize, ASZ + 16);
    attn_flash<<<BB*HH, 256, ASZ + 16>>>();

    gemm_tc<1><<<dim3(CC/128, BT/128), 256, gsmem>>>(bp, out);
}